// round 1
// baseline (speedup 1.0000x reference)
#include <cuda_runtime.h>
#include <math.h>

#define HD 128
#define NB 16     // batches
#define NV 4      // vocab
#define NL 6      // layers
#define MAXN 20000
#define MAXE 600000

// ---------------- scratch (static device allocs; cudaMalloc is banned) -----
__device__ float g_hV[MAXN * HD];       // working node features
__device__ float g_agg[MAXN * HD];      // scatter accumulator
__device__ float g_tmp[MAXN * HD];      // pre-LN residual sum
__device__ float g_ffn[MAXN * 4 * HD];  // FFN hidden
__device__ float g_deg[MAXN];
__device__ float g_pool[NB * HD];
__device__ float g_pcnt[NB];

// ---------------- tiny utility kernels -------------------------------------
__global__ void zero_kernel(float* __restrict__ p, int n) {
    int i = blockIdx.x * blockDim.x + threadIdx.x;
    if (i < n) p[i] = 0.f;
}

__global__ void copy_kernel(float* __restrict__ dst, const float* __restrict__ src, int n) {
    int i = blockIdx.x * blockDim.x + threadIdx.x;
    if (i < n) dst[i] = src[i];
}

__global__ void deg_kernel(const int* __restrict__ src, float* __restrict__ deg, int E) {
    int i = blockIdx.x * blockDim.x + threadIdx.x;
    if (i < E) atomicAdd(&deg[src[i]], 1.f);
}

// ---------------- fused edge MLP: gather + 3 GEMMs + scatter ---------------
// Per CTA: 128 edges x 128 outputs. 256 threads, 8x8 microtile each.
// Stage 1: C1 = relu([hE | hV[src] | hV[dst]] @ W1 + b1)   (K = 384)
// Stage 2: C2 = relu(C1 @ W2 + b2)                         (K = 128)
// Stage 3: m  = C2 @ W3 + b3 ; atomicAdd into agg[src]
#define EDGE_SMEM ((128*129 + 32*132 + 32*128) * 4 + 256 * 4)

__global__ __launch_bounds__(256, 2)
void edge_mlp_kernel(const float* __restrict__ hE,
                     const float* __restrict__ hV,
                     const int* __restrict__ esrc,
                     const int* __restrict__ edst,
                     const float* __restrict__ W1, const float* __restrict__ b1,
                     const float* __restrict__ W2, const float* __restrict__ b2,
                     const float* __restrict__ W3, const float* __restrict__ b3,
                     float* __restrict__ agg, int E)
{
    extern __shared__ float sm[];
    float* Cs = sm;                 // [128][129] inter-stage activations
    float* As = Cs + 128 * 129;     // [32][132]  gathered A chunk (k-major)
    float* Bs = As + 32 * 132;      // [32][128]  weight chunk
    int* s_src = (int*)(Bs + 32 * 128);
    int* s_dst = s_src + 128;

    const int tid = threadIdx.x;
    const int tx = tid & 15;        // output-col group
    const int ty = tid >> 4;        // edge-row group
    const int e0 = blockIdx.x * 128;

    if (tid < 128) {
        int e = e0 + tid;
        s_src[tid] = (e < E) ? esrc[e] : -1;
        s_dst[tid] = (e < E) ? edst[e] : -1;
    }
    __syncthreads();

    float acc[8][8];
#pragma unroll
    for (int i = 0; i < 8; i++)
#pragma unroll
        for (int j = 0; j < 8; j++) acc[i][j] = 0.f;

    // ---- stage 1 (K = 384, 12 chunks of 32) ----
    for (int c = 0; c < 12; ++c) {
#pragma unroll
        for (int it = 0; it < 4; ++it) {
            int item = tid + it * 256;          // 1024 float4 = 128 rows x 8
            int row = item >> 3;
            int q = item & 7;
            float4 v = make_float4(0.f, 0.f, 0.f, 0.f);
            int e = e0 + row;
            if (e < E) {
                const float* p;
                if (c < 4)      p = hE + (size_t)e * HD + c * 32;
                else if (c < 8) p = hV + (size_t)s_src[row] * HD + (c - 4) * 32;
                else            p = hV + (size_t)s_dst[row] * HD + (c - 8) * 32;
                v = *(const float4*)(p + q * 4);
            }
            int kk = q * 4;
            As[(kk + 0) * 132 + row] = v.x;
            As[(kk + 1) * 132 + row] = v.y;
            As[(kk + 2) * 132 + row] = v.z;
            As[(kk + 3) * 132 + row] = v.w;
        }
#pragma unroll
        for (int it = 0; it < 4; ++it) {
            int item = tid + it * 256;
            int k = item >> 5, qi = item & 31;
            *(float4*)&Bs[k * 128 + qi * 4] =
                *(const float4*)(W1 + (size_t)(c * 32 + k) * 128 + qi * 4);
        }
        __syncthreads();
#pragma unroll 4
        for (int k = 0; k < 32; ++k) {
            float a[8], b[8];
            *(float4*)&a[0] = *(float4*)&As[k * 132 + ty * 8];
            *(float4*)&a[4] = *(float4*)&As[k * 132 + ty * 8 + 4];
            *(float4*)&b[0] = *(float4*)&Bs[k * 128 + tx * 8];
            *(float4*)&b[4] = *(float4*)&Bs[k * 128 + tx * 8 + 4];
#pragma unroll
            for (int i = 0; i < 8; i++)
#pragma unroll
                for (int j = 0; j < 8; j++) acc[i][j] += a[i] * b[j];
        }
        __syncthreads();
    }
    {
        float bb[8];
#pragma unroll
        for (int j = 0; j < 8; j++) bb[j] = b1[tx * 8 + j];
#pragma unroll
        for (int i = 0; i < 8; i++)
#pragma unroll
            for (int j = 0; j < 8; j++)
                Cs[(ty * 8 + i) * 129 + tx * 8 + j] = fmaxf(acc[i][j] + bb[j], 0.f);
    }
    __syncthreads();

    // ---- stages 2 & 3 (K = 128, A comes from Cs) ----
    for (int s = 0; s < 2; ++s) {
        const float* W = s ? W3 : W2;
        const float* bias = s ? b3 : b2;
#pragma unroll
        for (int i = 0; i < 8; i++)
#pragma unroll
            for (int j = 0; j < 8; j++) acc[i][j] = 0.f;
        for (int kc = 0; kc < 4; ++kc) {
#pragma unroll
            for (int it = 0; it < 4; ++it) {
                int item = tid + it * 256;
                int k = item >> 5, qi = item & 31;
                *(float4*)&Bs[k * 128 + qi * 4] =
                    *(const float4*)(W + (size_t)(kc * 32 + k) * 128 + qi * 4);
            }
            __syncthreads();
#pragma unroll 4
            for (int k = 0; k < 32; ++k) {
                float a[8], b[8];
#pragma unroll
                for (int i = 0; i < 8; i++)
                    a[i] = Cs[(ty * 8 + i) * 129 + kc * 32 + k];
                *(float4*)&b[0] = *(float4*)&Bs[k * 128 + tx * 8];
                *(float4*)&b[4] = *(float4*)&Bs[k * 128 + tx * 8 + 4];
#pragma unroll
                for (int i = 0; i < 8; i++)
#pragma unroll
                    for (int j = 0; j < 8; j++) acc[i][j] += a[i] * b[j];
            }
            __syncthreads();
        }
        float bb[8];
#pragma unroll
        for (int j = 0; j < 8; j++) bb[j] = bias[tx * 8 + j];
        if (s == 0) {
#pragma unroll
            for (int i = 0; i < 8; i++)
#pragma unroll
                for (int j = 0; j < 8; j++)
                    Cs[(ty * 8 + i) * 129 + tx * 8 + j] = fmaxf(acc[i][j] + bb[j], 0.f);
            __syncthreads();
        } else {
#pragma unroll
            for (int i = 0; i < 8; i++) {
                int node = s_src[ty * 8 + i];
                if (node >= 0) {
                    float* dstp = agg + (size_t)node * HD + tx * 8;
#pragma unroll
                    for (int j = 0; j < 8; j++)
                        atomicAdd(dstp + j, acc[i][j] + bb[j]);
                }
            }
        }
    }
}

// ---------------- generic 128x128-tiled GEMM (row-major A[M,K] @ B[K,N]) ---
// epi 0: C = relu(A@B + bias) ; epi 1: C = A@B + bias + res (res is [M,N])
__global__ __launch_bounds__(256, 2)
void gemm_kernel(const float* __restrict__ A, const float* __restrict__ B,
                 const float* __restrict__ bias, const float* __restrict__ res,
                 float* __restrict__ C, int M, int N, int K, int epi)
{
    __shared__ float As[32 * 132];
    __shared__ float Bs[32 * 128];
    const int tid = threadIdx.x;
    const int tx = tid & 15, ty = tid >> 4;
    const int m0 = blockIdx.y * 128, n0 = blockIdx.x * 128;

    float acc[8][8];
#pragma unroll
    for (int i = 0; i < 8; i++)
#pragma unroll
        for (int j = 0; j < 8; j++) acc[i][j] = 0.f;

    const int nkc = K / 32;
    for (int kc = 0; kc < nkc; ++kc) {
#pragma unroll
        for (int it = 0; it < 4; ++it) {
            int item = tid + it * 256;
            int row = item >> 3, q = item & 7;
            float4 v = make_float4(0.f, 0.f, 0.f, 0.f);
            if (m0 + row < M)
                v = *(const float4*)(A + (size_t)(m0 + row) * K + kc * 32 + q * 4);
            int kk = q * 4;
            As[(kk + 0) * 132 + row] = v.x;
            As[(kk + 1) * 132 + row] = v.y;
            As[(kk + 2) * 132 + row] = v.z;
            As[(kk + 3) * 132 + row] = v.w;
        }
#pragma unroll
        for (int it = 0; it < 4; ++it) {
            int item = tid + it * 256;
            int k = item >> 5, qi = item & 31;
            *(float4*)&Bs[k * 128 + qi * 4] =
                *(const float4*)(B + (size_t)(kc * 32 + k) * N + n0 + qi * 4);
        }
        __syncthreads();
#pragma unroll 4
        for (int k = 0; k < 32; ++k) {
            float a[8], b[8];
            *(float4*)&a[0] = *(float4*)&As[k * 132 + ty * 8];
            *(float4*)&a[4] = *(float4*)&As[k * 132 + ty * 8 + 4];
            *(float4*)&b[0] = *(float4*)&Bs[k * 128 + tx * 8];
            *(float4*)&b[4] = *(float4*)&Bs[k * 128 + tx * 8 + 4];
#pragma unroll
            for (int i = 0; i < 8; i++)
#pragma unroll
                for (int j = 0; j < 8; j++) acc[i][j] += a[i] * b[j];
        }
        __syncthreads();
    }

    float bb[8];
#pragma unroll
    for (int j = 0; j < 8; j++) bb[j] = bias[n0 + tx * 8 + j];
#pragma unroll
    for (int i = 0; i < 8; i++) {
        int r = m0 + ty * 8 + i;
        if (r < M) {
#pragma unroll
            for (int j = 0; j < 8; j++) {
                int c = n0 + tx * 8 + j;
                float v = acc[i][j] + bb[j];
                if (epi == 0) v = fmaxf(v, 0.f);
                else          v += res[(size_t)r * N + c];
                C[(size_t)r * N + c] = v;
            }
        }
    }
}

// ---------------- layernorm kernels (one warp per node, H=128) -------------
__device__ __forceinline__ float warp_sum(float v) {
#pragma unroll
    for (int o = 16; o > 0; o >>= 1) v += __shfl_xor_sync(0xffffffffu, v, o);
    return v;
}

// hV = LN(hV + agg/deg) in place
__global__ void agg_ln_kernel(float* __restrict__ hV, const float* __restrict__ agg,
                              const float* __restrict__ deg,
                              const float* __restrict__ g, const float* __restrict__ b,
                              int N)
{
    int warp = (blockIdx.x * blockDim.x + threadIdx.x) >> 5;
    int lane = threadIdx.x & 31;
    if (warp >= N) return;
    float d = fmaxf(deg[warp], 1.f);
    float x[4];
#pragma unroll
    for (int j = 0; j < 4; j++) {
        int c = j * 32 + lane;
        x[j] = hV[(size_t)warp * HD + c] + agg[(size_t)warp * HD + c] / d;
    }
    float s = warp_sum(x[0] + x[1] + x[2] + x[3]);
    float mu = s * (1.f / HD);
    float ss = warp_sum(x[0]*x[0] + x[1]*x[1] + x[2]*x[2] + x[3]*x[3]);
    float var = ss * (1.f / HD) - mu * mu;
    float inv = rsqrtf(var + 1e-5f);
#pragma unroll
    for (int j = 0; j < 4; j++) {
        int c = j * 32 + lane;
        hV[(size_t)warp * HD + c] = (x[j] - mu) * inv * g[c] + b[c];
    }
}

// out = LN(x)
__global__ void ln_kernel(const float* __restrict__ x, float* __restrict__ out,
                          const float* __restrict__ g, const float* __restrict__ b,
                          int N)
{
    int warp = (blockIdx.x * blockDim.x + threadIdx.x) >> 5;
    int lane = threadIdx.x & 31;
    if (warp >= N) return;
    float v[4];
#pragma unroll
    for (int j = 0; j < 4; j++) v[j] = x[(size_t)warp * HD + j * 32 + lane];
    float s = warp_sum(v[0] + v[1] + v[2] + v[3]);
    float mu = s * (1.f / HD);
    float ss = warp_sum(v[0]*v[0] + v[1]*v[1] + v[2]*v[2] + v[3]*v[3]);
    float var = ss * (1.f / HD) - mu * mu;
    float inv = rsqrtf(var + 1e-5f);
#pragma unroll
    for (int j = 0; j < 4; j++) {
        int c = j * 32 + lane;
        out[(size_t)warp * HD + c] = (v[j] - mu) * inv * g[c] + b[c];
    }
}

// ---------------- pooling / heads ------------------------------------------
__global__ void pool_kernel(const float* __restrict__ hV, const int* __restrict__ batch_id,
                            float* __restrict__ pool, float* __restrict__ pcnt, int N)
{
    int i = blockIdx.x * blockDim.x + threadIdx.x;
    if (i < N * HD) {
        int n = i >> 7, c = i & 127;
        atomicAdd(&pool[batch_id[n] * HD + c], hV[i]);
    }
    if (i < N) atomicAdd(&pcnt[batch_id[i]], 1.f);
}

__global__ void head_kernel(const float* __restrict__ pool, const float* __restrict__ pcnt,
                            const float* __restrict__ P1, const float* __restrict__ P2,
                            const float* __restrict__ p2b, float* __restrict__ out)
{
    __shared__ float embs[NB * HD];
    __shared__ float t1[NB * HD];
    int tid = threadIdx.x;
    for (int i = tid; i < NB * HD; i += blockDim.x) {
        int bb = i >> 7;
        embs[i] = pool[i] / fmaxf(pcnt[bb], 1.f);
    }
    __syncthreads();
    for (int i = tid; i < NB * HD; i += blockDim.x) {
        int bb = i >> 7, j = i & 127;
        float s = 0.f;
        for (int k = 0; k < HD; k++) s += embs[bb * HD + k] * P1[k * HD + j];
        t1[i] = fmaxf(s, 0.f);
    }
    __syncthreads();
    for (int i = tid; i < NB * HD; i += blockDim.x) {
        int bb = i >> 7, j = i & 127;
        float s = p2b[j];
        for (int k = 0; k < HD; k++) s += t1[bb * HD + k] * P2[k * HD + j];
        out[i] = s;
    }
}

__global__ void logits_kernel(const float* __restrict__ hV, const int* __restrict__ S,
                              const float* __restrict__ R, const float* __restrict__ rb,
                              float* __restrict__ out, int N)
{
    __shared__ float Rs[HD * NV];
    __shared__ float rbs[NV];
    int tid = threadIdx.x;
    for (int i = tid; i < HD * NV; i += blockDim.x) Rs[i] = R[i];
    if (tid < NV) rbs[tid] = rb[tid];
    __syncthreads();
    int n = blockIdx.x * blockDim.x + tid;
    if (n < N) {
        float a0 = rbs[0], a1 = rbs[1], a2 = rbs[2], a3 = rbs[3];
        const float* h = hV + (size_t)n * HD;
#pragma unroll 8
        for (int k = 0; k < HD; k++) {
            float hv = h[k];
            a0 += hv * Rs[k * NV + 0];
            a1 += hv * Rs[k * NV + 1];
            a2 += hv * Rs[k * NV + 2];
            a3 += hv * Rs[k * NV + 3];
        }
        out[(size_t)n * NV + 0] = a0;
        out[(size_t)n * NV + 1] = a1;
        out[(size_t)n * NV + 2] = a2;
        out[(size_t)n * NV + 3] = a3;
        out[(size_t)N * NV + n] = (float)S[n];   // S value-cast into output
    }
}

// ---------------- launch ----------------------------------------------------
extern "C" void kernel_launch(void* const* d_in, const int* in_sizes, int n_in,
                              void* d_out, int out_size)
{
    const float* h_V  = (const float*)d_in[0];
    const float* h_E  = (const float*)d_in[1];
    const int*   Eidx = (const int*)d_in[2];
    const int*   bid  = (const int*)d_in[3];
    const int*   S    = (const int*)d_in[4];
    const float* W1   = (const float*)d_in[5];
    const float* b1   = (const float*)d_in[6];
    const float* W2   = (const float*)d_in[7];
    const float* b2   = (const float*)d_in[8];
    const float* W3   = (const float*)d_in[9];
    const float* b3   = (const float*)d_in[10];
    const float* ln1g = (const float*)d_in[11];
    const float* ln1b = (const float*)d_in[12];
    const float* Wi   = (const float*)d_in[13];
    const float* bi   = (const float*)d_in[14];
    const float* Wo   = (const float*)d_in[15];
    const float* bo   = (const float*)d_in[16];
    const float* ln2g = (const float*)d_in[17];
    const float* ln2b = (const float*)d_in[18];
    const float* P1   = (const float*)d_in[19];
    const float* P2   = (const float*)d_in[20];
    const float* p2b  = (const float*)d_in[21];
    const float* R    = (const float*)d_in[22];
    const float* rb   = (const float*)d_in[23];

    const int N = in_sizes[0] / HD;
    const int E = in_sizes[2] / 2;
    const int* esrc = Eidx;
    const int* edst = Eidx + E;

    float *p_hV, *p_agg, *p_tmp, *p_ffn, *p_deg, *p_pool, *p_pcnt;
    cudaGetSymbolAddress((void**)&p_hV,   g_hV);
    cudaGetSymbolAddress((void**)&p_agg,  g_agg);
    cudaGetSymbolAddress((void**)&p_tmp,  g_tmp);
    cudaGetSymbolAddress((void**)&p_ffn,  g_ffn);
    cudaGetSymbolAddress((void**)&p_deg,  g_deg);
    cudaGetSymbolAddress((void**)&p_pool, g_pool);
    cudaGetSymbolAddress((void**)&p_pcnt, g_pcnt);

    cudaFuncSetAttribute(edge_mlp_kernel,
                         cudaFuncAttributeMaxDynamicSharedMemorySize, EDGE_SMEM);

    // working copy of node features (inputs must stay pristine across replays)
    copy_kernel<<<(N * HD + 255) / 256, 256>>>(p_hV, h_V, N * HD);

    // in-degree (receiving node = src)
    zero_kernel<<<(N + 255) / 256, 256>>>(p_deg, N);
    deg_kernel<<<(E + 255) / 256, 256>>>(esrc, p_deg, E);

    const int edge_grid = (E + 127) / 128;
    const int mtiles = (N + 127) / 128;

    for (int l = 0; l < NL; ++l) {
        zero_kernel<<<(N * HD + 255) / 256, 256>>>(p_agg, N * HD);
        edge_mlp_kernel<<<edge_grid, 256, EDGE_SMEM>>>(
            h_E, p_hV, esrc, edst,
            W1 + (size_t)l * 3 * HD * HD, b1 + (size_t)l * HD,
            W2 + (size_t)l * HD * HD,     b2 + (size_t)l * HD,
            W3 + (size_t)l * HD * HD,     b3 + (size_t)l * HD,
            p_agg, E);
        agg_ln_kernel<<<(N + 7) / 8, 256>>>(p_hV, p_agg, p_deg,
                                            ln1g + (size_t)l * HD, ln1b + (size_t)l * HD, N);
        // FFN up: [N,128] @ [128,512] + bi, relu
        gemm_kernel<<<dim3(4, mtiles), 256>>>(
            p_hV, Wi + (size_t)l * HD * 4 * HD, bi + (size_t)l * 4 * HD,
            nullptr, p_ffn, N, 4 * HD, HD, 0);
        // FFN down + residual: [N,512] @ [512,128] + bo + hV
        gemm_kernel<<<dim3(1, mtiles), 256>>>(
            p_ffn, Wo + (size_t)l * 4 * HD * HD, bo + (size_t)l * HD,
            p_hV, p_tmp, N, HD, 4 * HD, 1);
        ln_kernel<<<(N + 7) / 8, 256>>>(p_tmp, p_hV,
                                        ln2g + (size_t)l * HD, ln2b + (size_t)l * HD, N);
    }

    // per-graph mean pooling + projection head
    zero_kernel<<<(NB * HD + 255) / 256, 256>>>(p_pool, NB * HD);
    zero_kernel<<<1, 32>>>(p_pcnt, NB);
    pool_kernel<<<(N * HD + 255) / 256, 256>>>(p_hV, bid, p_pool, p_pcnt, N);

    float* out = (float*)d_out;
    head_kernel<<<1, 256>>>(p_pool, p_pcnt, P1, P2, p2b,
                            out + (size_t)N * NV + N);
    logits_kernel<<<(N + 255) / 256, 256>>>(p_hV, S, R, rb, out, N);
}

// round 3
// speedup vs baseline: 2.6754x; 2.6754x over previous
#include <cuda_runtime.h>
#include <math.h>

#define HD 128
#define NB 16     // batches
#define NV 4      // vocab
#define NL 6      // layers
#define MAXN 20000
#define MAXE 600000

// ---------------- scratch (static device allocs; cudaMalloc is banned) -----
__device__ float g_hV[MAXN * HD];       // working node features
__device__ float g_agg[MAXN * HD];      // scatter accumulator
__device__ float g_tmp[MAXN * HD];      // pre-LN residual sum
__device__ float g_ffn[MAXN * 4 * HD];  // FFN hidden
__device__ float g_xvs[MAXN * HD];      // h_V @ W1_src
__device__ float g_xvd[MAXN * HD];      // h_V @ W1_dst
__device__ float g_deg[MAXN];
__device__ float g_pool[NB * HD];
__device__ float g_pcnt[NB];

// ---------------- tiny utility kernels -------------------------------------
__global__ void zero_kernel(float* __restrict__ p, int n) {
    int i = blockIdx.x * blockDim.x + threadIdx.x;
    if (i < n) p[i] = 0.f;
}

__global__ void copy_kernel(float* __restrict__ dst, const float* __restrict__ src, int n) {
    int i = blockIdx.x * blockDim.x + threadIdx.x;
    if (i < n) dst[i] = src[i];
}

__global__ void deg_kernel(const int* __restrict__ src, float* __restrict__ deg, int E) {
    int i = blockIdx.x * blockDim.x + threadIdx.x;
    if (i < E) atomicAdd(&deg[src[i]], 1.f);
}

// ---------------- tf32 helpers ---------------------------------------------
__device__ __forceinline__ unsigned f2tf(float f) {
    unsigned r;
    asm("cvt.rna.tf32.f32 %0, %1;" : "=r"(r) : "f"(f));
    return r;
}

__device__ __forceinline__ void mma_tf32(float c[4],
                                         unsigned a0, unsigned a1, unsigned a2, unsigned a3,
                                         unsigned b0, unsigned b1) {
    asm volatile(
        "mma.sync.aligned.m16n8k8.row.col.f32.tf32.tf32.f32 "
        "{%0,%1,%2,%3}, {%4,%5,%6,%7}, {%8,%9}, {%0,%1,%2,%3};"
        : "+f"(c[0]), "+f"(c[1]), "+f"(c[2]), "+f"(c[3])
        : "r"(a0), "r"(a1), "r"(a2), "r"(a3), "r"(b0), "r"(b1));
}

// 32-k-step MMA over one B chunk. A is smem tf32 [128][apitch] starting at k0.
__device__ __forceinline__ void mma_tile_k32(float acc[4][4][4],
                                             const unsigned* __restrict__ A, int apitch,
                                             const unsigned* __restrict__ Bs,
                                             int mrow0, int ncol0, int k0, int lane)
{
    const int lq = lane >> 2;   // 0..7
    const int lr = lane & 3;    // 0..3
#pragma unroll
    for (int kk = 0; kk < 32; kk += 8) {
        unsigned a[4][4], b[4][2];
#pragma unroll
        for (int mi = 0; mi < 4; ++mi) {
            const unsigned* p = A + (mrow0 + mi * 16 + lq) * apitch + k0 + kk + lr;
            a[mi][0] = p[0];
            a[mi][1] = p[8 * apitch];
            a[mi][2] = p[4];
            a[mi][3] = p[8 * apitch + 4];
        }
#pragma unroll
        for (int ni = 0; ni < 4; ++ni) {
            int c = ncol0 + ni * 8 + lq;
            b[ni][0] = Bs[(kk + lr) * 132 + c];
            b[ni][1] = Bs[(kk + 4 + lr) * 132 + c];
        }
#pragma unroll
        for (int mi = 0; mi < 4; ++mi)
#pragma unroll
            for (int ni = 0; ni < 4; ++ni)
                mma_tf32(acc[mi][ni], a[mi][0], a[mi][1], a[mi][2], a[mi][3],
                         b[ni][0], b[ni][1]);
    }
}

__device__ __forceinline__ void load_B_chunk(unsigned* __restrict__ Bs,
                                             const float* __restrict__ W,
                                             int kc, int tid)
{
#pragma unroll
    for (int it = 0; it < 4; ++it) {
        int item = tid + it * 256;
        int k = item >> 5, q = item & 31;
        const float4 v = *(const float4*)(W + (size_t)(kc * 32 + k) * HD + q * 4);
        unsigned* d = Bs + k * 132 + q * 4;
        d[0] = f2tf(v.x); d[1] = f2tf(v.y); d[2] = f2tf(v.z); d[3] = f2tf(v.w);
    }
}

// ---------------- fused edge MLP (tf32 tensor cores) ------------------------
// Per CTA: 128 edges x 128 outputs, 256 threads (8 warps, 2x4), warp tile 64x32.
// Stage 1: C1 = relu(hE @ W1a + XVs[src] + XVd[dst] + b1)    (K = 128)
// Stage 2: C2 = relu(C1 @ W2 + b2)                           (K = 128)
// Stage 3: m  = C2 @ W3 + b3 ; red.v4 scatter into agg[src]
#define EDGE_SMEM ((128 * 132 + 128 * 36 + 32 * 132) * 4 + 256 * 4)

__global__ __launch_bounds__(256, 2)
void edge_mlp_tc(const float* __restrict__ hE,
                 const int* __restrict__ esrc,
                 const int* __restrict__ edst,
                 const float* __restrict__ XVs,
                 const float* __restrict__ XVd,
                 const float* __restrict__ W1a, const float* __restrict__ b1,
                 const float* __restrict__ W2,  const float* __restrict__ b2,
                 const float* __restrict__ W3,  const float* __restrict__ b3,
                 float* __restrict__ agg, int E)
{
    extern __shared__ unsigned smem_u[];
    unsigned* Cs = smem_u;                    // [128][132] tf32 activations
    unsigned* As = Cs + 128 * 132;            // [128][36]  tf32 hE chunk
    unsigned* Bs = As + 128 * 36;             // [32][132]  tf32 weight chunk
    int* s_src = (int*)(Bs + 32 * 132);
    int* s_dst = s_src + 128;

    const int tid = threadIdx.x;
    const int lane = tid & 31;
    const int wid = tid >> 5;
    const int mrow0 = (wid >> 2) * 64;
    const int ncol0 = (wid & 3) * 32;
    const int lq = lane >> 2;
    const int lr = lane & 3;
    const int e0 = blockIdx.x * 128;

    if (tid < 128) {
        int e = e0 + tid;
        s_src[tid] = (e < E) ? esrc[e] : -1;
        s_dst[tid] = (e < E) ? edst[e] : -1;
    }
    __syncthreads();

    float acc[4][4][4];

    // ================= stage 1: hE @ W1a =================
#pragma unroll
    for (int mi = 0; mi < 4; ++mi)
#pragma unroll
        for (int ni = 0; ni < 4; ++ni)
#pragma unroll
            for (int j = 0; j < 4; ++j) acc[mi][ni][j] = 0.f;

    for (int kc = 0; kc < 4; ++kc) {
        // load + cvt A chunk: 128 rows x 32 k
#pragma unroll
        for (int it = 0; it < 4; ++it) {
            int item = tid + it * 256;
            int row = item >> 3, q = item & 7;
            float4 v = make_float4(0.f, 0.f, 0.f, 0.f);
            if (e0 + row < E)
                v = *(const float4*)(hE + (size_t)(e0 + row) * HD + kc * 32 + q * 4);
            unsigned* d = As + row * 36 + q * 4;
            d[0] = f2tf(v.x); d[1] = f2tf(v.y); d[2] = f2tf(v.z); d[3] = f2tf(v.w);
        }
        load_B_chunk(Bs, W1a, kc, tid);
        __syncthreads();
        mma_tile_k32(acc, As, 36, Bs, mrow0, ncol0, 0, lane);
        __syncthreads();
    }
    // epilogue 1: + b1 + XVs[src] + XVd[dst], relu, tf32 -> Cs
#pragma unroll
    for (int ni = 0; ni < 4; ++ni) {
        int c0 = ncol0 + ni * 8 + 2 * lr;
        float b10 = b1[c0], b11 = b1[c0 + 1];
#pragma unroll
        for (int mi = 0; mi < 4; ++mi) {
#pragma unroll
            for (int h = 0; h < 2; ++h) {
                int r = mrow0 + mi * 16 + lq + h * 8;
                int ns = s_src[r], nd = s_dst[r];
                float v0 = 0.f, v1 = 0.f;
                if (ns >= 0) {
                    v0 = acc[mi][ni][h * 2 + 0] + b10
                       + XVs[(size_t)ns * HD + c0] + XVd[(size_t)nd * HD + c0];
                    v1 = acc[mi][ni][h * 2 + 1] + b11
                       + XVs[(size_t)ns * HD + c0 + 1] + XVd[(size_t)nd * HD + c0 + 1];
                }
                Cs[r * 132 + c0]     = f2tf(fmaxf(v0, 0.f));
                Cs[r * 132 + c0 + 1] = f2tf(fmaxf(v1, 0.f));
            }
        }
    }
    __syncthreads();

    // ================= stage 2: C1 @ W2 =================
#pragma unroll
    for (int mi = 0; mi < 4; ++mi)
#pragma unroll
        for (int ni = 0; ni < 4; ++ni)
#pragma unroll
            for (int j = 0; j < 4; ++j) acc[mi][ni][j] = 0.f;

    for (int kc = 0; kc < 4; ++kc) {
        load_B_chunk(Bs, W2, kc, tid);
        __syncthreads();
        mma_tile_k32(acc, Cs, 132, Bs, mrow0, ncol0, kc * 32, lane);
        __syncthreads();
    }
    // epilogue 2: + b2, relu, tf32 -> Cs (all reads of Cs are done)
#pragma unroll
    for (int ni = 0; ni < 4; ++ni) {
        int c0 = ncol0 + ni * 8 + 2 * lr;
        float b20 = b2[c0], b21 = b2[c0 + 1];
#pragma unroll
        for (int mi = 0; mi < 4; ++mi) {
#pragma unroll
            for (int h = 0; h < 2; ++h) {
                int r = mrow0 + mi * 16 + lq + h * 8;
                Cs[r * 132 + c0]     = f2tf(fmaxf(acc[mi][ni][h * 2 + 0] + b20, 0.f));
                Cs[r * 132 + c0 + 1] = f2tf(fmaxf(acc[mi][ni][h * 2 + 1] + b21, 0.f));
            }
        }
    }
    __syncthreads();

    // ================= stage 3: C2 @ W3 =================
#pragma unroll
    for (int mi = 0; mi < 4; ++mi)
#pragma unroll
        for (int ni = 0; ni < 4; ++ni)
#pragma unroll
            for (int j = 0; j < 4; ++j) acc[mi][ni][j] = 0.f;

    for (int kc = 0; kc < 4; ++kc) {
        load_B_chunk(Bs, W3, kc, tid);
        __syncthreads();
        mma_tile_k32(acc, Cs, 132, Bs, mrow0, ncol0, kc * 32, lane);
        __syncthreads();
    }
    // epilogue 3: + b3, stage as f32 in Cs
    float* CsF = (float*)Cs;
#pragma unroll
    for (int ni = 0; ni < 4; ++ni) {
        int c0 = ncol0 + ni * 8 + 2 * lr;
        float b30 = b3[c0], b31 = b3[c0 + 1];
#pragma unroll
        for (int mi = 0; mi < 4; ++mi) {
#pragma unroll
            for (int h = 0; h < 2; ++h) {
                int r = mrow0 + mi * 16 + lq + h * 8;
                CsF[r * 132 + c0]     = acc[mi][ni][h * 2 + 0] + b30;
                CsF[r * 132 + c0 + 1] = acc[mi][ni][h * 2 + 1] + b31;
            }
        }
    }
    __syncthreads();

    // cooperative vector scatter: 128 rows x 32 float4
    for (int item = tid; item < 128 * 32; item += 256) {
        int row = item >> 5, q = item & 31;
        int node = s_src[row];
        if (node >= 0) {
            const float4 v = *(const float4*)(CsF + row * 132 + q * 4);
            float* p = agg + (size_t)node * HD + q * 4;
            asm volatile("red.global.add.v4.f32 [%0], {%1,%2,%3,%4};"
                         :: "l"(p), "f"(v.x), "f"(v.y), "f"(v.z), "f"(v.w)
                         : "memory");
        }
    }
}

// ---------------- generic 128x128-tiled fp32 GEMM ---------------------------
// epi 0: relu(A@B + bias); epi 1: A@B + bias + res; epi 2: A@B (no bias)
__global__ __launch_bounds__(256, 2)
void gemm_kernel(const float* __restrict__ A, const float* __restrict__ B,
                 const float* __restrict__ bias, const float* __restrict__ res,
                 float* __restrict__ C, int M, int N, int K, int epi)
{
    __shared__ float As[32 * 132];
    __shared__ float Bs[32 * 128];
    const int tid = threadIdx.x;
    const int tx = tid & 15, ty = tid >> 4;
    const int m0 = blockIdx.y * 128, n0 = blockIdx.x * 128;

    float acc[8][8];
#pragma unroll
    for (int i = 0; i < 8; i++)
#pragma unroll
        for (int j = 0; j < 8; j++) acc[i][j] = 0.f;

    const int nkc = K / 32;
    for (int kc = 0; kc < nkc; ++kc) {
#pragma unroll
        for (int it = 0; it < 4; ++it) {
            int item = tid + it * 256;
            int row = item >> 3, q = item & 7;
            float4 v = make_float4(0.f, 0.f, 0.f, 0.f);
            if (m0 + row < M)
                v = *(const float4*)(A + (size_t)(m0 + row) * K + kc * 32 + q * 4);
            int kk = q * 4;
            As[(kk + 0) * 132 + row] = v.x;
            As[(kk + 1) * 132 + row] = v.y;
            As[(kk + 2) * 132 + row] = v.z;
            As[(kk + 3) * 132 + row] = v.w;
        }
#pragma unroll
        for (int it = 0; it < 4; ++it) {
            int item = tid + it * 256;
            int k = item >> 5, qi = item & 31;
            *(float4*)&Bs[k * 128 + qi * 4] =
                *(const float4*)(B + (size_t)(kc * 32 + k) * N + n0 + qi * 4);
        }
        __syncthreads();
#pragma unroll 4
        for (int k = 0; k < 32; ++k) {
            float a[8], b[8];
            *(float4*)&a[0] = *(float4*)&As[k * 132 + ty * 8];
            *(float4*)&a[4] = *(float4*)&As[k * 132 + ty * 8 + 4];
            *(float4*)&b[0] = *(float4*)&Bs[k * 128 + tx * 8];
            *(float4*)&b[4] = *(float4*)&Bs[k * 128 + tx * 8 + 4];
#pragma unroll
            for (int i = 0; i < 8; i++)
#pragma unroll
                for (int j = 0; j < 8; j++) acc[i][j] += a[i] * b[j];
        }
        __syncthreads();
    }

    float bb[8];
#pragma unroll
    for (int j = 0; j < 8; j++) bb[j] = (epi == 2) ? 0.f : bias[n0 + tx * 8 + j];
#pragma unroll
    for (int i = 0; i < 8; i++) {
        int r = m0 + ty * 8 + i;
        if (r < M) {
#pragma unroll
            for (int j = 0; j < 8; j++) {
                int c = n0 + tx * 8 + j;
                float v = acc[i][j] + bb[j];
                if (epi == 0) v = fmaxf(v, 0.f);
                else if (epi == 1) v += res[(size_t)r * N + c];
                C[(size_t)r * N + c] = v;
            }
        }
    }
}

// ---------------- layernorm kernels (one warp per node, H=128) -------------
__device__ __forceinline__ float warp_sum(float v) {
#pragma unroll
    for (int o = 16; o > 0; o >>= 1) v += __shfl_xor_sync(0xffffffffu, v, o);
    return v;
}

// hV = LN(hV + agg/deg) in place
__global__ void agg_ln_kernel(float* __restrict__ hV, const float* __restrict__ agg,
                              const float* __restrict__ deg,
                              const float* __restrict__ g, const float* __restrict__ b,
                              int N)
{
    int warp = (blockIdx.x * blockDim.x + threadIdx.x) >> 5;
    int lane = threadIdx.x & 31;
    if (warp >= N) return;
    float d = fmaxf(deg[warp], 1.f);
    float x[4];
#pragma unroll
    for (int j = 0; j < 4; j++) {
        int c = j * 32 + lane;
        x[j] = hV[(size_t)warp * HD + c] + agg[(size_t)warp * HD + c] / d;
    }
    float s = warp_sum(x[0] + x[1] + x[2] + x[3]);
    float mu = s * (1.f / HD);
    float ss = warp_sum(x[0]*x[0] + x[1]*x[1] + x[2]*x[2] + x[3]*x[3]);
    float var = ss * (1.f / HD) - mu * mu;
    float inv = rsqrtf(var + 1e-5f);
#pragma unroll
    for (int j = 0; j < 4; j++) {
        int c = j * 32 + lane;
        hV[(size_t)warp * HD + c] = (x[j] - mu) * inv * g[c] + b[c];
    }
}

// out = LN(x)
__global__ void ln_kernel(const float* __restrict__ x, float* __restrict__ out,
                          const float* __restrict__ g, const float* __restrict__ b,
                          int N)
{
    int warp = (blockIdx.x * blockDim.x + threadIdx.x) >> 5;
    int lane = threadIdx.x & 31;
    if (warp >= N) return;
    float v[4];
#pragma unroll
    for (int j = 0; j < 4; j++) v[j] = x[(size_t)warp * HD + j * 32 + lane];
    float s = warp_sum(v[0] + v[1] + v[2] + v[3]);
    float mu = s * (1.f / HD);
    float ss = warp_sum(v[0]*v[0] + v[1]*v[1] + v[2]*v[2] + v[3]*v[3]);
    float var = ss * (1.f / HD) - mu * mu;
    float inv = rsqrtf(var + 1e-5f);
#pragma unroll
    for (int j = 0; j < 4; j++) {
        int c = j * 32 + lane;
        out[(size_t)warp * HD + c] = (v[j] - mu) * inv * g[c] + b[c];
    }
}

// ---------------- pooling / heads ------------------------------------------
__global__ void pool_kernel(const float* __restrict__ hV, const int* __restrict__ batch_id,
                            float* __restrict__ pool, float* __restrict__ pcnt, int N)
{
    int i = blockIdx.x * blockDim.x + threadIdx.x;
    if (i < N * HD) {
        int n = i >> 7, c = i & 127;
        atomicAdd(&pool[batch_id[n] * HD + c], hV[i]);
    }
    if (i < N) atomicAdd(&pcnt[batch_id[i]], 1.f);
}

__global__ void head_kernel(const float* __restrict__ pool, const float* __restrict__ pcnt,
                            const float* __restrict__ P1, const float* __restrict__ P2,
                            const float* __restrict__ p2b, float* __restrict__ out)
{
    __shared__ float embs[NB * HD];
    __shared__ float t1[NB * HD];
    int tid = threadIdx.x;
    for (int i = tid; i < NB * HD; i += blockDim.x) {
        int bb = i >> 7;
        embs[i] = pool[i] / fmaxf(pcnt[bb], 1.f);
    }
    __syncthreads();
    for (int i = tid; i < NB * HD; i += blockDim.x) {
        int bb = i >> 7, j = i & 127;
        float s = 0.f;
        for (int k = 0; k < HD; k++) s += embs[bb * HD + k] * P1[k * HD + j];
        t1[i] = fmaxf(s, 0.f);
    }
    __syncthreads();
    for (int i = tid; i < NB * HD; i += blockDim.x) {
        int bb = i >> 7, j = i & 127;
        float s = p2b[j];
        for (int k = 0; k < HD; k++) s += t1[bb * HD + k] * P2[k * HD + j];
        out[i] = s;
    }
}

__global__ void logits_kernel(const float* __restrict__ hV, const int* __restrict__ S,
                              const float* __restrict__ R, const float* __restrict__ rb,
                              float* __restrict__ out, int N)
{
    __shared__ float Rs[HD * NV];
    __shared__ float rbs[NV];
    int tid = threadIdx.x;
    for (int i = tid; i < HD * NV; i += blockDim.x) Rs[i] = R[i];
    if (tid < NV) rbs[tid] = rb[tid];
    __syncthreads();
    int n = blockIdx.x * blockDim.x + tid;
    if (n < N) {
        float a0 = rbs[0], a1 = rbs[1], a2 = rbs[2], a3 = rbs[3];
        const float* h = hV + (size_t)n * HD;
#pragma unroll 8
        for (int k = 0; k < HD; k++) {
            float hv = h[k];
            a0 += hv * Rs[k * NV + 0];
            a1 += hv * Rs[k * NV + 1];
            a2 += hv * Rs[k * NV + 2];
            a3 += hv * Rs[k * NV + 3];
        }
        out[(size_t)n * NV + 0] = a0;
        out[(size_t)n * NV + 1] = a1;
        out[(size_t)n * NV + 2] = a2;
        out[(size_t)n * NV + 3] = a3;
        out[(size_t)N * NV + n] = (float)S[n];   // S value-cast into output
    }
}

// ---------------- launch ----------------------------------------------------
extern "C" void kernel_launch(void* const* d_in, const int* in_sizes, int n_in,
                              void* d_out, int out_size)
{
    const float* h_V  = (const float*)d_in[0];
    const float* h_E  = (const float*)d_in[1];
    const int*   Eidx = (const int*)d_in[2];
    const int*   bid  = (const int*)d_in[3];
    const int*   S    = (const int*)d_in[4];
    const float* W1   = (const float*)d_in[5];
    const float* b1   = (const float*)d_in[6];
    const float* W2   = (const float*)d_in[7];
    const float* b2   = (const float*)d_in[8];
    const float* W3   = (const float*)d_in[9];
    const float* b3   = (const float*)d_in[10];
    const float* ln1g = (const float*)d_in[11];
    const float* ln1b = (const float*)d_in[12];
    const float* Wi   = (const float*)d_in[13];
    const float* bi   = (const float*)d_in[14];
    const float* Wo   = (const float*)d_in[15];
    const float* bo   = (const float*)d_in[16];
    const float* ln2g = (const float*)d_in[17];
    const float* ln2b = (const float*)d_in[18];
    const float* P1   = (const float*)d_in[19];
    const float* P2   = (const float*)d_in[20];
    const float* p2b  = (const float*)d_in[21];
    const float* R    = (const float*)d_in[22];
    const float* rb   = (const float*)d_in[23];

    const int N = in_sizes[0] / HD;
    const int E = in_sizes[2] / 2;
    const int* esrc = Eidx;
    const int* edst = Eidx + E;

    float *p_hV, *p_agg, *p_tmp, *p_ffn, *p_xvs, *p_xvd, *p_deg, *p_pool, *p_pcnt;
    cudaGetSymbolAddress((void**)&p_hV,   g_hV);
    cudaGetSymbolAddress((void**)&p_agg,  g_agg);
    cudaGetSymbolAddress((void**)&p_tmp,  g_tmp);
    cudaGetSymbolAddress((void**)&p_ffn,  g_ffn);
    cudaGetSymbolAddress((void**)&p_xvs,  g_xvs);
    cudaGetSymbolAddress((void**)&p_xvd,  g_xvd);
    cudaGetSymbolAddress((void**)&p_deg,  g_deg);
    cudaGetSymbolAddress((void**)&p_pool, g_pool);
    cudaGetSymbolAddress((void**)&p_pcnt, g_pcnt);

    cudaFuncSetAttribute(edge_mlp_tc,
                         cudaFuncAttributeMaxDynamicSharedMemorySize, EDGE_SMEM);

    // working copy of node features (inputs must stay pristine across replays)
    copy_kernel<<<(N * HD + 255) / 256, 256>>>(p_hV, h_V, N * HD);

    // in-degree (receiving node = src)
    zero_kernel<<<(N + 255) / 256, 256>>>(p_deg, N);
    deg_kernel<<<(E + 255) / 256, 256>>>(esrc, p_deg, E);

    const int edge_grid = (E + 127) / 128;
    const int mtiles = (N + 127) / 128;

    for (int l = 0; l < NL; ++l) {
        const float* W1l = W1 + (size_t)l * 3 * HD * HD;
        // pre-GEMMs: XVs = hV @ W1[128:256], XVd = hV @ W1[256:384]
        gemm_kernel<<<dim3(1, mtiles), 256>>>(
            p_hV, W1l + (size_t)HD * HD, nullptr, nullptr, p_xvs, N, HD, HD, 2);
        gemm_kernel<<<dim3(1, mtiles), 256>>>(
            p_hV, W1l + (size_t)2 * HD * HD, nullptr, nullptr, p_xvd, N, HD, HD, 2);

        zero_kernel<<<(N * HD + 255) / 256, 256>>>(p_agg, N * HD);
        edge_mlp_tc<<<edge_grid, 256, EDGE_SMEM>>>(
            h_E, esrc, edst, p_xvs, p_xvd,
            W1l, b1 + (size_t)l * HD,
            W2 + (size_t)l * HD * HD, b2 + (size_t)l * HD,
            W3 + (size_t)l * HD * HD, b3 + (size_t)l * HD,
            p_agg, E);
        agg_ln_kernel<<<(N + 7) / 8, 256>>>(p_hV, p_agg, p_deg,
                                            ln1g + (size_t)l * HD, ln1b + (size_t)l * HD, N);
        // FFN up: [N,128] @ [128,512] + bi, relu
        gemm_kernel<<<dim3(4, mtiles), 256>>>(
            p_hV, Wi + (size_t)l * HD * 4 * HD, bi + (size_t)l * 4 * HD,
            nullptr, p_ffn, N, 4 * HD, HD, 0);
        // FFN down + residual: [N,512] @ [512,128] + bo + hV
        gemm_kernel<<<dim3(1, mtiles), 256>>>(
            p_ffn, Wo + (size_t)l * 4 * HD * HD, bo + (size_t)l * HD,
            p_hV, p_tmp, N, HD, 4 * HD, 1);
        ln_kernel<<<(N + 7) / 8, 256>>>(p_tmp, p_hV,
                                        ln2g + (size_t)l * HD, ln2b + (size_t)l * HD, N);
    }

    // per-graph mean pooling + projection head
    zero_kernel<<<(NB * HD + 255) / 256, 256>>>(p_pool, NB * HD);
    zero_kernel<<<1, 32>>>(p_pcnt, NB);
    pool_kernel<<<(N * HD + 255) / 256, 256>>>(p_hV, bid, p_pool, p_pcnt, N);

    float* out = (float*)d_out;
    head_kernel<<<1, 256>>>(p_pool, p_pcnt, P1, P2, p2b,
                            out + (size_t)N * NV + N);
    logits_kernel<<<(N + 255) / 256, 256>>>(p_hV, S, R, rb, out, N);
}

// round 4
// speedup vs baseline: 3.4024x; 1.2717x over previous
#include <cuda_runtime.h>
#include <math.h>

#define HD 128
#define NB 16     // batches
#define NV 4      // vocab
#define NL 6      // layers
#define MAXN 20000
#define MAXE 600000

// ---------------- scratch (static device allocs; cudaMalloc is banned) -----
__device__ float g_hV[MAXN * HD];       // working node features
__device__ float g_agg[MAXN * HD];      // scatter accumulator
__device__ float g_tmp[MAXN * HD];      // pre-LN residual sum
__device__ float g_ffn[MAXN * 4 * HD];  // FFN hidden
__device__ float g_xvs[MAXN * HD];      // h_V @ W1_src
__device__ float g_xvd[MAXN * HD];      // h_V @ W1_dst
__device__ float g_deg[MAXN];
__device__ float g_pool[NB * HD];
__device__ float g_pcnt[NB];

// ---------------- tiny utility kernels -------------------------------------
__global__ void zero_kernel(float* __restrict__ p, int n) {
    int i = blockIdx.x * blockDim.x + threadIdx.x;
    if (i < n) p[i] = 0.f;
}

__global__ void copy_kernel(float* __restrict__ dst, const float* __restrict__ src, int n) {
    int i = blockIdx.x * blockDim.x + threadIdx.x;
    if (i < n) dst[i] = src[i];
}

__global__ void deg_kernel(const int* __restrict__ src, float* __restrict__ deg, int E) {
    int i = blockIdx.x * blockDim.x + threadIdx.x;
    if (i < E) atomicAdd(&deg[src[i]], 1.f);
}

// ---------------- tf32 + fragment-major helpers ------------------------------
// Fragment-major smem layouts for mma.m16n8k8:
//  A: group g = mtile*GS + ktile.  word = g*132 + lane*4 + comp   (uint4 reads)
//     comp: 0=(r,k) 1=(r+8,k) 2=(r,k+4) 3=(r+8,k+4); lane=(r%8)*4+(k%4)
//  B: group gb = ktile*16 + ntile. word = gb*66 + lane*2 + comp   (uint2 reads)
//     comp: 0=(K0+lr,N0+lq) 1=(K0+4+lr,N0+lq); lane=(n%8)*4+(k%4)

__device__ __forceinline__ unsigned f2tf(float f) {
    unsigned r;
    asm("cvt.rna.tf32.f32 %0, %1;" : "=r"(r) : "f"(f));
    return r;
}

__device__ __forceinline__ void mma_tf32(float c[4],
                                         unsigned a0, unsigned a1, unsigned a2, unsigned a3,
                                         unsigned b0, unsigned b1) {
    asm volatile(
        "mma.sync.aligned.m16n8k8.row.col.f32.tf32.tf32.f32 "
        "{%0,%1,%2,%3}, {%4,%5,%6,%7}, {%8,%9}, {%0,%1,%2,%3};"
        : "+f"(c[0]), "+f"(c[1]), "+f"(c[2]), "+f"(c[3])
        : "r"(a0), "r"(a1), "r"(a2), "r"(a3), "r"(b0), "r"(b1));
}

// load 128 rows x 32 k chunk from global row-major into fragment-major As (32 groups)
__device__ __forceinline__ void load_A_frag(unsigned* __restrict__ As,
                                            const float* __restrict__ A, size_t lda,
                                            int row0, int M, int kglob0, int tid)
{
#pragma unroll
    for (int it = 0; it < 4; ++it) {
        int item = tid + it * 256;
        int row = item >> 3;       // 0..127
        int q = item & 7;          // float4 within 32 k
        float4 v = make_float4(0.f, 0.f, 0.f, 0.f);
        if (row0 + row < M)
            v = *(const float4*)(A + (size_t)(row0 + row) * lda + kglob0 + q * 4);
        int g = ((row >> 4) << 2) + (q >> 1);
        int base = g * 132 + ((row & 7) << 4) + ((row >> 3) & 1) + ((q & 1) << 1);
        As[base + 0]  = f2tf(v.x);
        As[base + 4]  = f2tf(v.y);
        As[base + 8]  = f2tf(v.z);
        As[base + 12] = f2tf(v.w);
    }
}

// load 32 k x 128 n chunk of row-major B[K, ldb] into fragment-major Bs (64 groups)
__device__ __forceinline__ void load_B_frag(unsigned* __restrict__ Bs,
                                            const float* __restrict__ B, size_t ldb,
                                            int kglob0, int n0, int tid)
{
#pragma unroll
    for (int it = 0; it < 4; ++it) {
        int item = tid + it * 256;
        int k = item >> 5;     // 0..31
        int q = item & 31;     // float4 within 128 n
        const float4 v = *(const float4*)(B + (size_t)(kglob0 + k) * ldb + n0 + q * 4);
        int gb = ((k >> 3) << 4) + (q >> 1);
        int base = gb * 66 + ((q & 1) << 5) + ((k & 3) << 1) + ((k >> 2) & 1);
        Bs[base + 0]  = f2tf(v.x);
        Bs[base + 8]  = f2tf(v.y);
        Bs[base + 16] = f2tf(v.z);
        Bs[base + 24] = f2tf(v.w);
    }
}

// one 32-k chunk of warp-tile 64x32 mma. Af fragment-major with group stride gs per
// mtile; mg0 = first mtile group, gk0 = first ktile within groups; Bs per-chunk.
__device__ __forceinline__ void mma_chunk(float acc[4][4][4],
                                          const unsigned* __restrict__ Af, int mg0, int gs, int gk0,
                                          const unsigned* __restrict__ Bs, int ng0, int lane)
{
#pragma unroll
    for (int kt = 0; kt < 4; ++kt) {
        uint4 a[4]; uint2 b[4];
#pragma unroll
        for (int mi = 0; mi < 4; ++mi)
            a[mi] = *(const uint4*)&Af[((mg0 + mi) * gs + gk0 + kt) * 132 + lane * 4];
#pragma unroll
        for (int ni = 0; ni < 4; ++ni)
            b[ni] = *(const uint2*)&Bs[((kt << 4) + ng0 + ni) * 66 + lane * 2];
#pragma unroll
        for (int mi = 0; mi < 4; ++mi)
#pragma unroll
            for (int ni = 0; ni < 4; ++ni)
                mma_tf32(acc[mi][ni], a[mi].x, a[mi].y, a[mi].z, a[mi].w,
                         b[ni].x, b[ni].y);
    }
}

// ---------------- fused edge MLP (tf32 tensor cores) ------------------------
// Per CTA: 128 edges x 128 outputs, 256 threads (8 warps 2x4), warp tile 64x32.
// Stage 1: C1 = relu(hE @ W1a + XVs[src] + XVd[dst] + b1)    (K = 128)
// Stage 2: C2 = relu(C1 @ W2 + b2)                           (K = 128)
// Stage 3: m  = C2 @ W3 + b3 ; red.v4 scatter into agg[src]
// Cs: 128 groups (8 mtiles x 16 ktiles) fragment-major = 16896 words
#define CS_WORDS (128 * 132)
#define AS_WORDS (32 * 132)
#define BS_WORDS (64 * 66)
#define EDGE_SMEM ((CS_WORDS + AS_WORDS + BS_WORDS + 256) * 4)

__global__ __launch_bounds__(256, 2)
void edge_mlp_tc(const float* __restrict__ hE,
                 const int* __restrict__ esrc,
                 const int* __restrict__ edst,
                 const float* __restrict__ XVs,
                 const float* __restrict__ XVd,
                 const float* __restrict__ W1a, const float* __restrict__ b1,
                 const float* __restrict__ W2,  const float* __restrict__ b2,
                 const float* __restrict__ W3,  const float* __restrict__ b3,
                 float* __restrict__ agg, int E)
{
    extern __shared__ unsigned smem_u[];
    unsigned* Cs = smem_u;                    // fragment-major activations / f32 staging
    unsigned* As = Cs + CS_WORDS;
    unsigned* Bs = As + AS_WORDS;
    int* s_src = (int*)(Bs + BS_WORDS);
    int* s_dst = s_src + 128;

    const int tid = threadIdx.x;
    const int lane = tid & 31;
    const int wid = tid >> 5;
    const int mrow0 = (wid >> 2) * 64;
    const int ncol0 = (wid & 3) * 32;
    const int mg0 = mrow0 >> 4;   // first mtile
    const int ng0 = ncol0 >> 3;   // first ntile
    const int lq = lane >> 2;
    const int lr = lane & 3;
    const int e0 = blockIdx.x * 128;

    if (tid < 128) {
        int e = e0 + tid;
        s_src[tid] = (e < E) ? esrc[e] : -1;
        s_dst[tid] = (e < E) ? edst[e] : -1;
    }
    __syncthreads();

    float acc[4][4][4];

    // ================= stage 1: hE @ W1a =================
#pragma unroll
    for (int mi = 0; mi < 4; ++mi)
#pragma unroll
        for (int ni = 0; ni < 4; ++ni)
#pragma unroll
            for (int j = 0; j < 4; ++j) acc[mi][ni][j] = 0.f;

    for (int kc = 0; kc < 4; ++kc) {
        load_A_frag(As, hE, HD, e0, E, kc * 32, tid);
        load_B_frag(Bs, W1a, HD, kc * 32, 0, tid);
        __syncthreads();
        mma_chunk(acc, As, mg0, 4, 0, Bs, ng0, lane);
        __syncthreads();
    }
    // epilogue 1: + b1 + XVs[src] + XVd[dst], relu, tf32 -> Cs fragment-major
#pragma unroll
    for (int ni = 0; ni < 4; ++ni) {
        int cb = ncol0 + ni * 8 + 2 * lr;
        float b10 = b1[cb], b11 = b1[cb + 1];
#pragma unroll
        for (int mi = 0; mi < 4; ++mi) {
#pragma unroll
            for (int h = 0; h < 2; ++h) {
                int r = mrow0 + mi * 16 + lq + h * 8;
                int ns = s_src[r], nd = s_dst[r];
                float v0 = 0.f, v1 = 0.f;
                if (ns >= 0) {
                    v0 = acc[mi][ni][h * 2 + 0] + b10
                       + XVs[(size_t)ns * HD + cb] + XVd[(size_t)nd * HD + cb];
                    v1 = acc[mi][ni][h * 2 + 1] + b11
                       + XVs[(size_t)ns * HD + cb + 1] + XVd[(size_t)nd * HD + cb + 1];
                }
#pragma unroll
                for (int e = 0; e < 2; ++e) {
                    int t = 2 * lr + e;
                    Cs[((mg0 + mi) * 16 + ng0 + ni) * 132
                       + ((lq * 4 + (t & 3)) << 2) + h + ((t >> 2) << 1)]
                        = f2tf(fmaxf(e ? v1 : v0, 0.f));
                }
            }
        }
    }
    __syncthreads();

    // ================= stage 2: C1 @ W2 =================
#pragma unroll
    for (int mi = 0; mi < 4; ++mi)
#pragma unroll
        for (int ni = 0; ni < 4; ++ni)
#pragma unroll
            for (int j = 0; j < 4; ++j) acc[mi][ni][j] = 0.f;

    for (int kc = 0; kc < 4; ++kc) {
        load_B_frag(Bs, W2, HD, kc * 32, 0, tid);
        __syncthreads();
        mma_chunk(acc, Cs, mg0, 16, kc * 4, Bs, ng0, lane);
        __syncthreads();
    }
    // epilogue 2: + b2, relu, tf32 -> Cs (all reads of Cs done after last sync)
#pragma unroll
    for (int ni = 0; ni < 4; ++ni) {
        int cb = ncol0 + ni * 8 + 2 * lr;
        float b20 = b2[cb], b21 = b2[cb + 1];
#pragma unroll
        for (int mi = 0; mi < 4; ++mi) {
#pragma unroll
            for (int h = 0; h < 2; ++h) {
#pragma unroll
                for (int e = 0; e < 2; ++e) {
                    int t = 2 * lr + e;
                    float v = acc[mi][ni][h * 2 + e] + (e ? b21 : b20);
                    Cs[((mg0 + mi) * 16 + ng0 + ni) * 132
                       + ((lq * 4 + (t & 3)) << 2) + h + ((t >> 2) << 1)]
                        = f2tf(fmaxf(v, 0.f));
                }
            }
        }
    }
    __syncthreads();

    // ================= stage 3: C2 @ W3 =================
#pragma unroll
    for (int mi = 0; mi < 4; ++mi)
#pragma unroll
        for (int ni = 0; ni < 4; ++ni)
#pragma unroll
            for (int j = 0; j < 4; ++j) acc[mi][ni][j] = 0.f;

    for (int kc = 0; kc < 4; ++kc) {
        load_B_frag(Bs, W3, HD, kc * 32, 0, tid);
        __syncthreads();
        mma_chunk(acc, Cs, mg0, 16, kc * 4, Bs, ng0, lane);
        __syncthreads();
    }
    // epilogue 3: + b3, stage f32 row-major (pitch 132) into Cs for scatter
    float* CsF = (float*)Cs;
#pragma unroll
    for (int ni = 0; ni < 4; ++ni) {
        int cb = ncol0 + ni * 8 + 2 * lr;
        float b30 = b3[cb], b31 = b3[cb + 1];
#pragma unroll
        for (int mi = 0; mi < 4; ++mi) {
#pragma unroll
            for (int h = 0; h < 2; ++h) {
                int r = mrow0 + mi * 16 + lq + h * 8;
                CsF[r * 132 + cb]     = acc[mi][ni][h * 2 + 0] + b30;
                CsF[r * 132 + cb + 1] = acc[mi][ni][h * 2 + 1] + b31;
            }
        }
    }
    __syncthreads();

    // cooperative vector scatter: 128 rows x 32 float4
    for (int item = tid; item < 128 * 32; item += 256) {
        int row = item >> 5, q = item & 31;
        int node = s_src[row];
        if (node >= 0) {
            const float4 v = *(const float4*)(CsF + row * 132 + q * 4);
            float* p = agg + (size_t)node * HD + q * 4;
            asm volatile("red.global.add.v4.f32 [%0], {%1,%2,%3,%4};"
                         :: "l"(p), "f"(v.x), "f"(v.y), "f"(v.z), "f"(v.w)
                         : "memory");
        }
    }
}

// ---------------- tf32 tensor-core node GEMM (128x128 tile) ----------------
// epi 0: relu(A@B + bias); epi 1: A@B + bias + res; epi 2: A@B
__global__ __launch_bounds__(256, 2)
void gemm_tc(const float* __restrict__ A, const float* __restrict__ B,
             const float* __restrict__ bias, const float* __restrict__ res,
             float* __restrict__ C, int M, int N, int K, int epi)
{
    __shared__ __align__(16) unsigned As[AS_WORDS];
    __shared__ __align__(16) unsigned Bs[BS_WORDS];
    const int tid = threadIdx.x;
    const int lane = tid & 31;
    const int wid = tid >> 5;
    const int mrow0 = (wid >> 2) * 64;
    const int ncol0 = (wid & 3) * 32;
    const int mg0 = mrow0 >> 4;
    const int ng0 = ncol0 >> 3;
    const int lq = lane >> 2;
    const int lr = lane & 3;
    const int m0 = blockIdx.y * 128, n0 = blockIdx.x * 128;

    float acc[4][4][4];
#pragma unroll
    for (int mi = 0; mi < 4; ++mi)
#pragma unroll
        for (int ni = 0; ni < 4; ++ni)
#pragma unroll
            for (int j = 0; j < 4; ++j) acc[mi][ni][j] = 0.f;

    const int nkc = K / 32;
    for (int kc = 0; kc < nkc; ++kc) {
        load_A_frag(As, A, K, m0, M, kc * 32, tid);
        load_B_frag(Bs, B, N, kc * 32, n0, tid);
        __syncthreads();
        mma_chunk(acc, As, mg0, 4, 0, Bs, ng0, lane);
        __syncthreads();
    }

#pragma unroll
    for (int ni = 0; ni < 4; ++ni) {
        int c = n0 + ncol0 + ni * 8 + 2 * lr;
        float bb0 = (epi == 2) ? 0.f : bias[c];
        float bb1 = (epi == 2) ? 0.f : bias[c + 1];
#pragma unroll
        for (int mi = 0; mi < 4; ++mi) {
#pragma unroll
            for (int h = 0; h < 2; ++h) {
                int r = m0 + mrow0 + mi * 16 + lq + h * 8;
                if (r < M) {
                    float v0 = acc[mi][ni][h * 2 + 0] + bb0;
                    float v1 = acc[mi][ni][h * 2 + 1] + bb1;
                    if (epi == 0) { v0 = fmaxf(v0, 0.f); v1 = fmaxf(v1, 0.f); }
                    else if (epi == 1) {
                        v0 += res[(size_t)r * N + c];
                        v1 += res[(size_t)r * N + c + 1];
                    }
                    C[(size_t)r * N + c]     = v0;
                    C[(size_t)r * N + c + 1] = v1;
                }
            }
        }
    }
}

// ---------------- layernorm kernels (one warp per node, H=128) -------------
__device__ __forceinline__ float warp_sum(float v) {
#pragma unroll
    for (int o = 16; o > 0; o >>= 1) v += __shfl_xor_sync(0xffffffffu, v, o);
    return v;
}

// hV = LN(hV + agg/deg) in place
__global__ void agg_ln_kernel(float* __restrict__ hV, const float* __restrict__ agg,
                              const float* __restrict__ deg,
                              const float* __restrict__ g, const float* __restrict__ b,
                              int N)
{
    int warp = (blockIdx.x * blockDim.x + threadIdx.x) >> 5;
    int lane = threadIdx.x & 31;
    if (warp >= N) return;
    float d = fmaxf(deg[warp], 1.f);
    float x[4];
#pragma unroll
    for (int j = 0; j < 4; j++) {
        int c = j * 32 + lane;
        x[j] = hV[(size_t)warp * HD + c] + agg[(size_t)warp * HD + c] / d;
    }
    float s = warp_sum(x[0] + x[1] + x[2] + x[3]);
    float mu = s * (1.f / HD);
    float ss = warp_sum(x[0]*x[0] + x[1]*x[1] + x[2]*x[2] + x[3]*x[3]);
    float var = ss * (1.f / HD) - mu * mu;
    float inv = rsqrtf(var + 1e-5f);
#pragma unroll
    for (int j = 0; j < 4; j++) {
        int c = j * 32 + lane;
        hV[(size_t)warp * HD + c] = (x[j] - mu) * inv * g[c] + b[c];
    }
}

// out = LN(x)
__global__ void ln_kernel(const float* __restrict__ x, float* __restrict__ out,
                          const float* __restrict__ g, const float* __restrict__ b,
                          int N)
{
    int warp = (blockIdx.x * blockDim.x + threadIdx.x) >> 5;
    int lane = threadIdx.x & 31;
    if (warp >= N) return;
    float v[4];
#pragma unroll
    for (int j = 0; j < 4; j++) v[j] = x[(size_t)warp * HD + j * 32 + lane];
    float s = warp_sum(v[0] + v[1] + v[2] + v[3]);
    float mu = s * (1.f / HD);
    float ss = warp_sum(v[0]*v[0] + v[1]*v[1] + v[2]*v[2] + v[3]*v[3]);
    float var = ss * (1.f / HD) - mu * mu;
    float inv = rsqrtf(var + 1e-5f);
#pragma unroll
    for (int j = 0; j < 4; j++) {
        int c = j * 32 + lane;
        out[(size_t)warp * HD + c] = (v[j] - mu) * inv * g[c] + b[c];
    }
}

// ---------------- pooling / heads ------------------------------------------
__global__ void pool_kernel(const float* __restrict__ hV, const int* __restrict__ batch_id,
                            float* __restrict__ pool, float* __restrict__ pcnt, int N)
{
    int i = blockIdx.x * blockDim.x + threadIdx.x;
    if (i < N * HD) {
        int n = i >> 7, c = i & 127;
        atomicAdd(&pool[batch_id[n] * HD + c], hV[i]);
    }
    if (i < N) atomicAdd(&pcnt[batch_id[i]], 1.f);
}

__global__ void head_kernel(const float* __restrict__ pool, const float* __restrict__ pcnt,
                            const float* __restrict__ P1, const float* __restrict__ P2,
                            const float* __restrict__ p2b, float* __restrict__ out)
{
    __shared__ float embs[NB * HD];
    __shared__ float t1[NB * HD];
    int tid = threadIdx.x;
    for (int i = tid; i < NB * HD; i += blockDim.x) {
        int bb = i >> 7;
        embs[i] = pool[i] / fmaxf(pcnt[bb], 1.f);
    }
    __syncthreads();
    for (int i = tid; i < NB * HD; i += blockDim.x) {
        int bb = i >> 7, j = i & 127;
        float s = 0.f;
        for (int k = 0; k < HD; k++) s += embs[bb * HD + k] * P1[k * HD + j];
        t1[i] = fmaxf(s, 0.f);
    }
    __syncthreads();
    for (int i = tid; i < NB * HD; i += blockDim.x) {
        int bb = i >> 7, j = i & 127;
        float s = p2b[j];
        for (int k = 0; k < HD; k++) s += t1[bb * HD + k] * P2[k * HD + j];
        out[i] = s;
    }
}

__global__ void logits_kernel(const float* __restrict__ hV, const int* __restrict__ S,
                              const float* __restrict__ R, const float* __restrict__ rb,
                              float* __restrict__ out, int N)
{
    __shared__ float Rs[HD * NV];
    __shared__ float rbs[NV];
    int tid = threadIdx.x;
    for (int i = tid; i < HD * NV; i += blockDim.x) Rs[i] = R[i];
    if (tid < NV) rbs[tid] = rb[tid];
    __syncthreads();
    int n = blockIdx.x * blockDim.x + tid;
    if (n < N) {
        float a0 = rbs[0], a1 = rbs[1], a2 = rbs[2], a3 = rbs[3];
        const float* h = hV + (size_t)n * HD;
#pragma unroll 8
        for (int k = 0; k < HD; k++) {
            float hv = h[k];
            a0 += hv * Rs[k * NV + 0];
            a1 += hv * Rs[k * NV + 1];
            a2 += hv * Rs[k * NV + 2];
            a3 += hv * Rs[k * NV + 3];
        }
        out[(size_t)n * NV + 0] = a0;
        out[(size_t)n * NV + 1] = a1;
        out[(size_t)n * NV + 2] = a2;
        out[(size_t)n * NV + 3] = a3;
        out[(size_t)N * NV + n] = (float)S[n];   // S value-cast into output
    }
}

// ---------------- launch ----------------------------------------------------
extern "C" void kernel_launch(void* const* d_in, const int* in_sizes, int n_in,
                              void* d_out, int out_size)
{
    const float* h_V  = (const float*)d_in[0];
    const float* h_E  = (const float*)d_in[1];
    const int*   Eidx = (const int*)d_in[2];
    const int*   bid  = (const int*)d_in[3];
    const int*   S    = (const int*)d_in[4];
    const float* W1   = (const float*)d_in[5];
    const float* b1   = (const float*)d_in[6];
    const float* W2   = (const float*)d_in[7];
    const float* b2   = (const float*)d_in[8];
    const float* W3   = (const float*)d_in[9];
    const float* b3   = (const float*)d_in[10];
    const float* ln1g = (const float*)d_in[11];
    const float* ln1b = (const float*)d_in[12];
    const float* Wi   = (const float*)d_in[13];
    const float* bi   = (const float*)d_in[14];
    const float* Wo   = (const float*)d_in[15];
    const float* bo   = (const float*)d_in[16];
    const float* ln2g = (const float*)d_in[17];
    const float* ln2b = (const float*)d_in[18];
    const float* P1   = (const float*)d_in[19];
    const float* P2   = (const float*)d_in[20];
    const float* p2b  = (const float*)d_in[21];
    const float* R    = (const float*)d_in[22];
    const float* rb   = (const float*)d_in[23];

    const int N = in_sizes[0] / HD;
    const int E = in_sizes[2] / 2;
    const int* esrc = Eidx;
    const int* edst = Eidx + E;

    float *p_hV, *p_agg, *p_tmp, *p_ffn, *p_xvs, *p_xvd, *p_deg, *p_pool, *p_pcnt;
    cudaGetSymbolAddress((void**)&p_hV,   g_hV);
    cudaGetSymbolAddress((void**)&p_agg,  g_agg);
    cudaGetSymbolAddress((void**)&p_tmp,  g_tmp);
    cudaGetSymbolAddress((void**)&p_ffn,  g_ffn);
    cudaGetSymbolAddress((void**)&p_xvs,  g_xvs);
    cudaGetSymbolAddress((void**)&p_xvd,  g_xvd);
    cudaGetSymbolAddress((void**)&p_deg,  g_deg);
    cudaGetSymbolAddress((void**)&p_pool, g_pool);
    cudaGetSymbolAddress((void**)&p_pcnt, g_pcnt);

    cudaFuncSetAttribute(edge_mlp_tc,
                         cudaFuncAttributeMaxDynamicSharedMemorySize, EDGE_SMEM);

    // working copy of node features (inputs must stay pristine across replays)
    copy_kernel<<<(N * HD + 255) / 256, 256>>>(p_hV, h_V, N * HD);

    // in-degree (receiving node = src)
    zero_kernel<<<(N + 255) / 256, 256>>>(p_deg, N);
    deg_kernel<<<(E + 255) / 256, 256>>>(esrc, p_deg, E);

    const int edge_grid = (E + 127) / 128;
    const int mtiles = (N + 127) / 128;

    for (int l = 0; l < NL; ++l) {
        const float* W1l = W1 + (size_t)l * 3 * HD * HD;
        // pre-GEMMs: XVs = hV @ W1[128:256], XVd = hV @ W1[256:384]
        gemm_tc<<<dim3(1, mtiles), 256>>>(
            p_hV, W1l + (size_t)HD * HD, nullptr, nullptr, p_xvs, N, HD, HD, 2);
        gemm_tc<<<dim3(1, mtiles), 256>>>(
            p_hV, W1l + (size_t)2 * HD * HD, nullptr, nullptr, p_xvd, N, HD, HD, 2);

        zero_kernel<<<(N * HD + 255) / 256, 256>>>(p_agg, N * HD);
        edge_mlp_tc<<<edge_grid, 256, EDGE_SMEM>>>(
            h_E, esrc, edst, p_xvs, p_xvd,
            W1l, b1 + (size_t)l * HD,
            W2 + (size_t)l * HD * HD, b2 + (size_t)l * HD,
            W3 + (size_t)l * HD * HD, b3 + (size_t)l * HD,
            p_agg, E);
        agg_ln_kernel<<<(N + 7) / 8, 256>>>(p_hV, p_agg, p_deg,
                                            ln1g + (size_t)l * HD, ln1b + (size_t)l * HD, N);
        // FFN up: [N,128] @ [128,512] + bi, relu
        gemm_tc<<<dim3(4, mtiles), 256>>>(
            p_hV, Wi + (size_t)l * HD * 4 * HD, bi + (size_t)l * 4 * HD,
            nullptr, p_ffn, N, 4 * HD, HD, 0);
        // FFN down + residual: [N,512] @ [512,128] + bo + hV
        gemm_tc<<<dim3(1, mtiles), 256>>>(
            p_ffn, Wo + (size_t)l * 4 * HD * HD, bo + (size_t)l * HD,
            p_hV, p_tmp, N, HD, 4 * HD, 1);
        ln_kernel<<<(N + 7) / 8, 256>>>(p_tmp, p_hV,
                                        ln2g + (size_t)l * HD, ln2b + (size_t)l * HD, N);
    }

    // per-graph mean pooling + projection head
    zero_kernel<<<(NB * HD + 255) / 256, 256>>>(p_pool, NB * HD);
    zero_kernel<<<1, 32>>>(p_pcnt, NB);
    pool_kernel<<<(N * HD + 255) / 256, 256>>>(p_hV, bid, p_pool, p_pcnt, N);

    float* out = (float*)d_out;
    head_kernel<<<1, 256>>>(p_pool, p_pcnt, P1, P2, p2b,
                            out + (size_t)N * NV + N);
    logits_kernel<<<(N + 255) / 256, 256>>>(p_hV, S, R, rb, out, N);
}

// round 5
// speedup vs baseline: 3.8293x; 1.1255x over previous
#include <cuda_runtime.h>
#include <math.h>

#define HD 128
#define NB 16     // batches
#define NV 4      // vocab
#define NL 6      // layers
#define MAXN 20000
#define MAXE 600000

// ---------------- scratch (static device allocs; cudaMalloc is banned) -----
__device__ float g_hV[MAXN * HD];       // working node features
__device__ float g_agg[MAXN * HD];      // scatter accumulator
__device__ float g_tmp[MAXN * HD];      // pre-LN residual sum
__device__ float g_ffn[MAXN * 4 * HD];  // FFN hidden
__device__ float g_xvs[MAXN * HD];      // h_V @ W1_src
__device__ float g_xvd[MAXN * HD];      // h_V @ W1_dst
__device__ float g_deg[MAXN];
__device__ float g_pool[NB * HD];
__device__ float g_pcnt[NB];

// ---------------- tiny utility kernels -------------------------------------
__global__ void zero_kernel(float* __restrict__ p, int n) {
    int i = blockIdx.x * blockDim.x + threadIdx.x;
    if (i < n) p[i] = 0.f;
}

__global__ void copy_kernel(float* __restrict__ dst, const float* __restrict__ src, int n) {
    int i = blockIdx.x * blockDim.x + threadIdx.x;
    if (i < n) dst[i] = src[i];
}

__global__ void deg_kernel(const int* __restrict__ src, float* __restrict__ deg, int E) {
    int i = blockIdx.x * blockDim.x + threadIdx.x;
    if (i < E) atomicAdd(&deg[src[i]], 1.f);
}

// ---------------- tf32 + fragment-major helpers ------------------------------
// Fragment-major smem layouts for mma.m16n8k8:
//  A: group g = mtile*GS + ktile.  word = g*132 + lane*4 + comp   (uint4 reads)
//  B: group gb = ktile*16 + ntile. word = gb*66 + lane*2 + comp   (uint2 reads)

__device__ __forceinline__ unsigned f2tf(float f) {
    unsigned r;
    asm("cvt.rna.tf32.f32 %0, %1;" : "=r"(r) : "f"(f));
    return r;
}

__device__ __forceinline__ void mma_tf32(float c[4],
                                         unsigned a0, unsigned a1, unsigned a2, unsigned a3,
                                         unsigned b0, unsigned b1) {
    asm volatile(
        "mma.sync.aligned.m16n8k8.row.col.f32.tf32.tf32.f32 "
        "{%0,%1,%2,%3}, {%4,%5,%6,%7}, {%8,%9}, {%0,%1,%2,%3};"
        : "+f"(c[0]), "+f"(c[1]), "+f"(c[2]), "+f"(c[3])
        : "r"(a0), "r"(a1), "r"(a2), "r"(a3), "r"(b0), "r"(b1));
}

// ---- split LDG / STS for A chunks (128 rows x 32 k) -> 32 groups, stride 132
__device__ __forceinline__ void ldg_A(float4 v[4], const float* __restrict__ A,
                                      size_t lda, int row0, int M, int kglob0, int tid)
{
#pragma unroll
    for (int it = 0; it < 4; ++it) {
        int item = tid + it * 256;
        int row = item >> 3, q = item & 7;
        v[it] = make_float4(0.f, 0.f, 0.f, 0.f);
        if (row0 + row < M)
            v[it] = *(const float4*)(A + (size_t)(row0 + row) * lda + kglob0 + q * 4);
    }
}

__device__ __forceinline__ void sts_A(unsigned* __restrict__ As, const float4 v[4], int tid)
{
#pragma unroll
    for (int it = 0; it < 4; ++it) {
        int item = tid + it * 256;
        int row = item >> 3, q = item & 7;
        int g = ((row >> 4) << 2) + (q >> 1);
        int base = g * 132 + ((row & 7) << 4) + ((row >> 3) & 1) + ((q & 1) << 1);
        As[base + 0]  = f2tf(v[it].x);
        As[base + 4]  = f2tf(v[it].y);
        As[base + 8]  = f2tf(v[it].z);
        As[base + 12] = f2tf(v[it].w);
    }
}

// ---- split LDG / STS for B chunks (32 k x 128 n) -> 64 groups, stride 66
__device__ __forceinline__ void ldg_B(float4 v[4], const float* __restrict__ B,
                                      size_t ldb, int kglob0, int n0, int tid)
{
#pragma unroll
    for (int it = 0; it < 4; ++it) {
        int item = tid + it * 256;
        int k = item >> 5, q = item & 31;
        v[it] = *(const float4*)(B + (size_t)(kglob0 + k) * ldb + n0 + q * 4);
    }
}

__device__ __forceinline__ void sts_B(unsigned* __restrict__ Bs, const float4 v[4], int tid)
{
#pragma unroll
    for (int it = 0; it < 4; ++it) {
        int item = tid + it * 256;
        int k = item >> 5, q = item & 31;
        int gb = ((k >> 3) << 4) + (q >> 1);
        int base = gb * 66 + ((q & 1) << 5) + ((k & 3) << 1) + ((k >> 2) & 1);
        Bs[base + 0]  = f2tf(v[it].x);
        Bs[base + 8]  = f2tf(v[it].y);
        Bs[base + 16] = f2tf(v[it].z);
        Bs[base + 24] = f2tf(v[it].w);
    }
}

// one 32-k chunk of warp-tile 64x32 mma
__device__ __forceinline__ void mma_chunk(float acc[4][4][4],
                                          const unsigned* __restrict__ Af, int mg0, int gs, int gk0,
                                          const unsigned* __restrict__ Bs, int ng0, int lane)
{
#pragma unroll
    for (int kt = 0; kt < 4; ++kt) {
        uint4 a[4]; uint2 b[4];
#pragma unroll
        for (int mi = 0; mi < 4; ++mi)
            a[mi] = *(const uint4*)&Af[((mg0 + mi) * gs + gk0 + kt) * 132 + lane * 4];
#pragma unroll
        for (int ni = 0; ni < 4; ++ni)
            b[ni] = *(const uint2*)&Bs[((kt << 4) + ng0 + ni) * 66 + lane * 2];
#pragma unroll
        for (int mi = 0; mi < 4; ++mi)
#pragma unroll
            for (int ni = 0; ni < 4; ++ni)
                mma_tf32(acc[mi][ni], a[mi].x, a[mi].y, a[mi].z, a[mi].w,
                         b[ni].x, b[ni].y);
    }
}

#define ACC_ZERO(acc) \
    _Pragma("unroll") for (int mi = 0; mi < 4; ++mi) \
    _Pragma("unroll") for (int ni = 0; ni < 4; ++ni) \
    _Pragma("unroll") for (int j = 0; j < 4; ++j) acc[mi][ni][j] = 0.f;

// ---------------- fused edge MLP (tf32 tensor cores, pipelined) -------------
// Per CTA: 128 edges x 128 outputs, 256 threads (8 warps 2x4), warp tile 64x32.
// smem: WB = W1a resident (4 chunks x 4224), aliased as Cs after stage 1.
//       As = stage-1 A chunk, then W2/W3 streaming chunk.
#define WB_WORDS (4 * 64 * 66)     // 16896 = also 128 groups * 132 for Cs
#define ASB_WORDS (32 * 132)       // 4224
#define EDGE_SMEM ((WB_WORDS + ASB_WORDS + 256) * 4)

__global__ __launch_bounds__(256, 2)
void edge_mlp_tc(const float* __restrict__ hE,
                 const int* __restrict__ esrc,
                 const int* __restrict__ edst,
                 const float* __restrict__ XVs,
                 const float* __restrict__ XVd,
                 const float* __restrict__ W1a, const float* __restrict__ b1,
                 const float* __restrict__ W2,  const float* __restrict__ b2,
                 const float* __restrict__ W3,  const float* __restrict__ b3,
                 float* __restrict__ agg, int E)
{
    extern __shared__ unsigned smem_u[];
    unsigned* WB = smem_u;            // W1a resident; later Cs (fragment-major)
    unsigned* As = WB + WB_WORDS;     // stage-1 A chunk; later W2/W3 chunk
    int* s_src = (int*)(As + ASB_WORDS);
    int* s_dst = s_src + 128;

    const int tid = threadIdx.x;
    const int lane = tid & 31;
    const int wid = tid >> 5;
    const int mrow0 = (wid >> 2) * 64;
    const int ncol0 = (wid & 3) * 32;
    const int mg0 = mrow0 >> 4;
    const int ng0 = ncol0 >> 3;
    const int lq = lane >> 2;
    const int lr = lane & 3;
    const int e0 = blockIdx.x * 128;

    if (tid < 128) {
        int e = e0 + tid;
        s_src[tid] = (e < E) ? esrc[e] : -1;
        s_dst[tid] = (e < E) ? edst[e] : -1;
    }

    float4 v[4];
    float acc[4][4][4];

    // ================= stage 1: hE @ W1a (W resident, A pipelined) ==========
    ACC_ZERO(acc);
    // preload full W1a (4 chunks) + A chunk 0
#pragma unroll
    for (int c = 0; c < 4; ++c) {
        ldg_B(v, W1a, HD, c * 32, 0, tid);
        sts_B(WB + c * 4224, v, tid);
    }
    ldg_A(v, hE, HD, e0, E, 0, tid);
    sts_A(As, v, tid);
    __syncthreads();

#pragma unroll
    for (int kc = 0; kc < 4; ++kc) {
        if (kc < 3) ldg_A(v, hE, HD, e0, E, (kc + 1) * 32, tid);
        mma_chunk(acc, As, mg0, 4, 0, WB + kc * 4224, ng0, lane);
        __syncthreads();
        if (kc < 3) { sts_A(As, v, tid); __syncthreads(); }
    }

    unsigned* Cs = WB;   // alias — all W1a reads are done (sync above)

    // epilogue 1: + b1 + XVs[src] + XVd[dst], relu, tf32 -> Cs fragment-major
#pragma unroll
    for (int ni = 0; ni < 4; ++ni) {
        int cb = ncol0 + ni * 8 + 2 * lr;
        float b10 = b1[cb], b11 = b1[cb + 1];
#pragma unroll
        for (int mi = 0; mi < 4; ++mi) {
#pragma unroll
            for (int h = 0; h < 2; ++h) {
                int r = mrow0 + mi * 16 + lq + h * 8;
                int ns = s_src[r], nd = s_dst[r];
                float v0 = 0.f, v1 = 0.f;
                if (ns >= 0) {
                    float2 xs = *(const float2*)(XVs + (size_t)ns * HD + cb);
                    float2 xd = *(const float2*)(XVd + (size_t)nd * HD + cb);
                    v0 = acc[mi][ni][h * 2 + 0] + b10 + xs.x + xd.x;
                    v1 = acc[mi][ni][h * 2 + 1] + b11 + xs.y + xd.y;
                }
#pragma unroll
                for (int e = 0; e < 2; ++e) {
                    int t = 2 * lr + e;
                    Cs[((mg0 + mi) * 16 + ng0 + ni) * 132
                       + ((lq * 4 + (t & 3)) << 2) + h + ((t >> 2) << 1)]
                        = f2tf(fmaxf(e ? v1 : v0, 0.f));
                }
            }
        }
    }

    // ================= stage 2: C1 @ W2 (B pipelined through As) ============
    ACC_ZERO(acc);
    ldg_B(v, W2, HD, 0, 0, tid);
    sts_B(As, v, tid);
    __syncthreads();   // also publishes epilogue-1 Cs stores

#pragma unroll
    for (int kc = 0; kc < 4; ++kc) {
        if (kc < 3) ldg_B(v, W2, HD, (kc + 1) * 32, 0, tid);
        mma_chunk(acc, Cs, mg0, 16, kc * 4, As, ng0, lane);
        __syncthreads();
        if (kc < 3) { sts_B(As, v, tid); __syncthreads(); }
    }

    // epilogue 2: + b2, relu, tf32 -> Cs (in place, own slots)
#pragma unroll
    for (int ni = 0; ni < 4; ++ni) {
        int cb = ncol0 + ni * 8 + 2 * lr;
        float b20 = b2[cb], b21 = b2[cb + 1];
#pragma unroll
        for (int mi = 0; mi < 4; ++mi) {
#pragma unroll
            for (int h = 0; h < 2; ++h) {
#pragma unroll
                for (int e = 0; e < 2; ++e) {
                    int t = 2 * lr + e;
                    float vv = acc[mi][ni][h * 2 + e] + (e ? b21 : b20);
                    Cs[((mg0 + mi) * 16 + ng0 + ni) * 132
                       + ((lq * 4 + (t & 3)) << 2) + h + ((t >> 2) << 1)]
                        = f2tf(fmaxf(vv, 0.f));
                }
            }
        }
    }

    // ================= stage 3: C2 @ W3 =================
    ACC_ZERO(acc);
    ldg_B(v, W3, HD, 0, 0, tid);
    sts_B(As, v, tid);
    __syncthreads();

#pragma unroll
    for (int kc = 0; kc < 4; ++kc) {
        if (kc < 3) ldg_B(v, W3, HD, (kc + 1) * 32, 0, tid);
        mma_chunk(acc, Cs, mg0, 16, kc * 4, As, ng0, lane);
        __syncthreads();
        if (kc < 3) { sts_B(As, v, tid); __syncthreads(); }
    }

    // epilogue 3: + b3, stage f32 row-major (pitch 132) into Cs for scatter
    float* CsF = (float*)Cs;
#pragma unroll
    for (int ni = 0; ni < 4; ++ni) {
        int cb = ncol0 + ni * 8 + 2 * lr;
        float b30 = b3[cb], b31 = b3[cb + 1];
#pragma unroll
        for (int mi = 0; mi < 4; ++mi) {
#pragma unroll
            for (int h = 0; h < 2; ++h) {
                int r = mrow0 + mi * 16 + lq + h * 8;
                CsF[r * 132 + cb]     = acc[mi][ni][h * 2 + 0] + b30;
                CsF[r * 132 + cb + 1] = acc[mi][ni][h * 2 + 1] + b31;
            }
        }
    }
    __syncthreads();

    // cooperative vector scatter: 128 rows x 32 float4
    for (int item = tid; item < 128 * 32; item += 256) {
        int row = item >> 5, q = item & 31;
        int node = s_src[row];
        if (node >= 0) {
            const float4 vv = *(const float4*)(CsF + row * 132 + q * 4);
            float* p = agg + (size_t)node * HD + q * 4;
            asm volatile("red.global.add.v4.f32 [%0], {%1,%2,%3,%4};"
                         :: "l"(p), "f"(vv.x), "f"(vv.y), "f"(vv.z), "f"(vv.w)
                         : "memory");
        }
    }
}

// ---------------- tf32 tensor-core node GEMM (128x128 tile, B pipelined) ----
// epi 0: relu(A@B + bias); epi 1: A@B + bias + res; epi 2: A@B
// dual=1: blockIdx.z selects (B,C) or (B2,C2) (for the two pre-GEMMs)
__global__ __launch_bounds__(256, 2)
void gemm_tc(const float* __restrict__ A, const float* __restrict__ B,
             const float* __restrict__ B2,
             const float* __restrict__ bias, const float* __restrict__ res,
             float* __restrict__ C, float* __restrict__ C2,
             int M, int N, int K, int epi)
{
    __shared__ __align__(16) unsigned As[ASB_WORDS];
    __shared__ __align__(16) unsigned Bs[64 * 66];
    const int tid = threadIdx.x;
    const int lane = tid & 31;
    const int wid = tid >> 5;
    const int mrow0 = (wid >> 2) * 64;
    const int ncol0 = (wid & 3) * 32;
    const int mg0 = mrow0 >> 4;
    const int ng0 = ncol0 >> 3;
    const int lq = lane >> 2;
    const int lr = lane & 3;
    const int m0 = blockIdx.y * 128, n0 = blockIdx.x * 128;
    if (blockIdx.z) { B = B2; C = C2; }

    float4 va[4], vb[4];
    float acc[4][4][4];
    ACC_ZERO(acc);

    const int nkc = K / 32;
    ldg_A(va, A, K, m0, M, 0, tid);
    ldg_B(vb, B, N, 0, n0, tid);
    sts_A(As, va, tid);
    sts_B(Bs, vb, tid);
    __syncthreads();

    for (int kc = 0; kc < nkc; ++kc) {
        if (kc + 1 < nkc) {
            ldg_A(va, A, K, m0, M, (kc + 1) * 32, tid);
            ldg_B(vb, B, N, (kc + 1) * 32, n0, tid);
        }
        mma_chunk(acc, As, mg0, 4, 0, Bs, ng0, lane);
        __syncthreads();
        if (kc + 1 < nkc) {
            sts_A(As, va, tid);
            sts_B(Bs, vb, tid);
            __syncthreads();
        }
    }

#pragma unroll
    for (int ni = 0; ni < 4; ++ni) {
        int c = n0 + ncol0 + ni * 8 + 2 * lr;
        float bb0 = (epi == 2) ? 0.f : bias[c];
        float bb1 = (epi == 2) ? 0.f : bias[c + 1];
#pragma unroll
        for (int mi = 0; mi < 4; ++mi) {
#pragma unroll
            for (int h = 0; h < 2; ++h) {
                int r = m0 + mrow0 + mi * 16 + lq + h * 8;
                if (r < M) {
                    float v0 = acc[mi][ni][h * 2 + 0] + bb0;
                    float v1 = acc[mi][ni][h * 2 + 1] + bb1;
                    if (epi == 0) { v0 = fmaxf(v0, 0.f); v1 = fmaxf(v1, 0.f); }
                    else if (epi == 1) {
                        v0 += res[(size_t)r * N + c];
                        v1 += res[(size_t)r * N + c + 1];
                    }
                    C[(size_t)r * N + c]     = v0;
                    C[(size_t)r * N + c + 1] = v1;
                }
            }
        }
    }
}

// ---------------- layernorm kernels (one warp per node, H=128) -------------
__device__ __forceinline__ float warp_sum(float v) {
#pragma unroll
    for (int o = 16; o > 0; o >>= 1) v += __shfl_xor_sync(0xffffffffu, v, o);
    return v;
}

__global__ void agg_ln_kernel(float* __restrict__ hV, const float* __restrict__ agg,
                              const float* __restrict__ deg,
                              const float* __restrict__ g, const float* __restrict__ b,
                              int N)
{
    int warp = (blockIdx.x * blockDim.x + threadIdx.x) >> 5;
    int lane = threadIdx.x & 31;
    if (warp >= N) return;
    float d = fmaxf(deg[warp], 1.f);
    float x[4];
#pragma unroll
    for (int j = 0; j < 4; j++) {
        int c = j * 32 + lane;
        x[j] = hV[(size_t)warp * HD + c] + agg[(size_t)warp * HD + c] / d;
    }
    float s = warp_sum(x[0] + x[1] + x[2] + x[3]);
    float mu = s * (1.f / HD);
    float ss = warp_sum(x[0]*x[0] + x[1]*x[1] + x[2]*x[2] + x[3]*x[3]);
    float var = ss * (1.f / HD) - mu * mu;
    float inv = rsqrtf(var + 1e-5f);
#pragma unroll
    for (int j = 0; j < 4; j++) {
        int c = j * 32 + lane;
        hV[(size_t)warp * HD + c] = (x[j] - mu) * inv * g[c] + b[c];
    }
}

__global__ void ln_kernel(const float* __restrict__ x, float* __restrict__ out,
                          const float* __restrict__ g, const float* __restrict__ b,
                          int N)
{
    int warp = (blockIdx.x * blockDim.x + threadIdx.x) >> 5;
    int lane = threadIdx.x & 31;
    if (warp >= N) return;
    float v[4];
#pragma unroll
    for (int j = 0; j < 4; j++) v[j] = x[(size_t)warp * HD + j * 32 + lane];
    float s = warp_sum(v[0] + v[1] + v[2] + v[3]);
    float mu = s * (1.f / HD);
    float ss = warp_sum(v[0]*v[0] + v[1]*v[1] + v[2]*v[2] + v[3]*v[3]);
    float var = ss * (1.f / HD) - mu * mu;
    float inv = rsqrtf(var + 1e-5f);
#pragma unroll
    for (int j = 0; j < 4; j++) {
        int c = j * 32 + lane;
        out[(size_t)warp * HD + c] = (v[j] - mu) * inv * g[c] + b[c];
    }
}

// ---------------- pooling / heads ------------------------------------------
__global__ void pool_kernel(const float* __restrict__ hV, const int* __restrict__ batch_id,
                            float* __restrict__ pool, float* __restrict__ pcnt, int N)
{
    int i = blockIdx.x * blockDim.x + threadIdx.x;
    if (i < N * HD) {
        int n = i >> 7, c = i & 127;
        atomicAdd(&pool[batch_id[n] * HD + c], hV[i]);
    }
    if (i < N) atomicAdd(&pcnt[batch_id[i]], 1.f);
}

__global__ void head_kernel(const float* __restrict__ pool, const float* __restrict__ pcnt,
                            const float* __restrict__ P1, const float* __restrict__ P2,
                            const float* __restrict__ p2b, float* __restrict__ out)
{
    __shared__ float embs[NB * HD];
    __shared__ float t1[NB * HD];
    int tid = threadIdx.x;
    for (int i = tid; i < NB * HD; i += blockDim.x) {
        int bb = i >> 7;
        embs[i] = pool[i] / fmaxf(pcnt[bb], 1.f);
    }
    __syncthreads();
    for (int i = tid; i < NB * HD; i += blockDim.x) {
        int bb = i >> 7, j = i & 127;
        float s = 0.f;
        for (int k = 0; k < HD; k++) s += embs[bb * HD + k] * P1[k * HD + j];
        t1[i] = fmaxf(s, 0.f);
    }
    __syncthreads();
    for (int i = tid; i < NB * HD; i += blockDim.x) {
        int bb = i >> 7, j = i & 127;
        float s = p2b[j];
        for (int k = 0; k < HD; k++) s += t1[bb * HD + k] * P2[k * HD + j];
        out[i] = s;
    }
}

__global__ void logits_kernel(const float* __restrict__ hV, const int* __restrict__ S,
                              const float* __restrict__ R, const float* __restrict__ rb,
                              float* __restrict__ out, int N)
{
    __shared__ float Rs[HD * NV];
    __shared__ float rbs[NV];
    int tid = threadIdx.x;
    for (int i = tid; i < HD * NV; i += blockDim.x) Rs[i] = R[i];
    if (tid < NV) rbs[tid] = rb[tid];
    __syncthreads();
    int n = blockIdx.x * blockDim.x + tid;
    if (n < N) {
        float a0 = rbs[0], a1 = rbs[1], a2 = rbs[2], a3 = rbs[3];
        const float* h = hV + (size_t)n * HD;
#pragma unroll 8
        for (int k = 0; k < HD; k++) {
            float hv = h[k];
            a0 += hv * Rs[k * NV + 0];
            a1 += hv * Rs[k * NV + 1];
            a2 += hv * Rs[k * NV + 2];
            a3 += hv * Rs[k * NV + 3];
        }
        out[(size_t)n * NV + 0] = a0;
        out[(size_t)n * NV + 1] = a1;
        out[(size_t)n * NV + 2] = a2;
        out[(size_t)n * NV + 3] = a3;
        out[(size_t)N * NV + n] = (float)S[n];   // S value-cast into output
    }
}

// ---------------- launch ----------------------------------------------------
extern "C" void kernel_launch(void* const* d_in, const int* in_sizes, int n_in,
                              void* d_out, int out_size)
{
    const float* h_V  = (const float*)d_in[0];
    const float* h_E  = (const float*)d_in[1];
    const int*   Eidx = (const int*)d_in[2];
    const int*   bid  = (const int*)d_in[3];
    const int*   S    = (const int*)d_in[4];
    const float* W1   = (const float*)d_in[5];
    const float* b1   = (const float*)d_in[6];
    const float* W2   = (const float*)d_in[7];
    const float* b2   = (const float*)d_in[8];
    const float* W3   = (const float*)d_in[9];
    const float* b3   = (const float*)d_in[10];
    const float* ln1g = (const float*)d_in[11];
    const float* ln1b = (const float*)d_in[12];
    const float* Wi   = (const float*)d_in[13];
    const float* bi   = (const float*)d_in[14];
    const float* Wo   = (const float*)d_in[15];
    const float* bo   = (const float*)d_in[16];
    const float* ln2g = (const float*)d_in[17];
    const float* ln2b = (const float*)d_in[18];
    const float* P1   = (const float*)d_in[19];
    const float* P2   = (const float*)d_in[20];
    const float* p2b  = (const float*)d_in[21];
    const float* R    = (const float*)d_in[22];
    const float* rb   = (const float*)d_in[23];

    const int N = in_sizes[0] / HD;
    const int E = in_sizes[2] / 2;
    const int* esrc = Eidx;
    const int* edst = Eidx + E;

    float *p_hV, *p_agg, *p_tmp, *p_ffn, *p_xvs, *p_xvd, *p_deg, *p_pool, *p_pcnt;
    cudaGetSymbolAddress((void**)&p_hV,   g_hV);
    cudaGetSymbolAddress((void**)&p_agg,  g_agg);
    cudaGetSymbolAddress((void**)&p_tmp,  g_tmp);
    cudaGetSymbolAddress((void**)&p_ffn,  g_ffn);
    cudaGetSymbolAddress((void**)&p_xvs,  g_xvs);
    cudaGetSymbolAddress((void**)&p_xvd,  g_xvd);
    cudaGetSymbolAddress((void**)&p_deg,  g_deg);
    cudaGetSymbolAddress((void**)&p_pool, g_pool);
    cudaGetSymbolAddress((void**)&p_pcnt, g_pcnt);

    cudaFuncSetAttribute(edge_mlp_tc,
                         cudaFuncAttributeMaxDynamicSharedMemorySize, EDGE_SMEM);

    // working copy of node features (inputs must stay pristine across replays)
    copy_kernel<<<(N * HD + 255) / 256, 256>>>(p_hV, h_V, N * HD);

    // in-degree (receiving node = src)
    zero_kernel<<<(N + 255) / 256, 256>>>(p_deg, N);
    deg_kernel<<<(E + 255) / 256, 256>>>(esrc, p_deg, E);

    const int edge_grid = (E + 127) / 128;
    const int mtiles = (N + 127) / 128;

    for (int l = 0; l < NL; ++l) {
        const float* W1l = W1 + (size_t)l * 3 * HD * HD;
        // fused pre-GEMMs: XVs = hV @ W1[128:256], XVd = hV @ W1[256:384]
        gemm_tc<<<dim3(1, mtiles, 2), 256>>>(
            p_hV, W1l + (size_t)HD * HD, W1l + (size_t)2 * HD * HD,
            nullptr, nullptr, p_xvs, p_xvd, N, HD, HD, 2);

        zero_kernel<<<(N * HD + 255) / 256, 256>>>(p_agg, N * HD);
        edge_mlp_tc<<<edge_grid, 256, EDGE_SMEM>>>(
            h_E, esrc, edst, p_xvs, p_xvd,
            W1l, b1 + (size_t)l * HD,
            W2 + (size_t)l * HD * HD, b2 + (size_t)l * HD,
            W3 + (size_t)l * HD * HD, b3 + (size_t)l * HD,
            p_agg, E);
        agg_ln_kernel<<<(N + 7) / 8, 256>>>(p_hV, p_agg, p_deg,
                                            ln1g + (size_t)l * HD, ln1b + (size_t)l * HD, N);
        // FFN up: [N,128] @ [128,512] + bi, relu
        gemm_tc<<<dim3(4, mtiles, 1), 256>>>(
            p_hV, Wi + (size_t)l * HD * 4 * HD, nullptr,
            bi + (size_t)l * 4 * HD, nullptr, p_ffn, nullptr, N, 4 * HD, HD, 0);
        // FFN down + residual: [N,512] @ [512,128] + bo + hV
        gemm_tc<<<dim3(1, mtiles, 1), 256>>>(
            p_ffn, Wo + (size_t)l * 4 * HD * HD, nullptr,
            bo + (size_t)l * HD, p_hV, p_tmp, nullptr, N, HD, 4 * HD, 1);
        ln_kernel<<<(N + 7) / 8, 256>>>(p_tmp, p_hV,
                                        ln2g + (size_t)l * HD, ln2b + (size_t)l * HD, N);
    }

    // per-graph mean pooling + projection head
    zero_kernel<<<(NB * HD + 255) / 256, 256>>>(p_pool, NB * HD);
    zero_kernel<<<1, 32>>>(p_pcnt, NB);
    pool_kernel<<<(N * HD + 255) / 256, 256>>>(p_hV, bid, p_pool, p_pcnt, N);

    float* out = (float*)d_out;
    head_kernel<<<1, 256>>>(p_pool, p_pcnt, P1, P2, p2b,
                            out + (size_t)N * NV + N);
    logits_kernel<<<(N + 255) / 256, 256>>>(p_hV, S, R, rb, out, N);
}